// round 2
// baseline (speedup 1.0000x reference)
#include <cuda_runtime.h>
#include <cuda_bf16.h>
#include <math.h>

#define NN 100000
#define EE 1600000
#define FHID 64

// Scratch (device globals: allocation-free rule)
__device__ float g_h[(size_t)NN * FHID];   // gemm output
__device__ float g_a[(size_t)NN * FHID];   // aggregation output
__device__ float g_t[NN];                  // layer-3 projected scalar
__device__ int   g_deg[NN];
__device__ float g_dis[NN];
__device__ int   g_idx[(size_t)2 * EE];    // normalized int32 edge indices
__device__ int   g_is64;                   // dtype flag

// ---------------- edge dtype detection + normalization ----------------
// If the edge buffer is int64 (values < 2^31), every odd 32-bit word is 0.
__global__ void k_detect(const unsigned* __restrict__ buf, int nwords) {
    __shared__ unsigned s[256];
    unsigned acc = 0;
    for (int i = threadIdx.x; i < nwords; i += 256) acc |= buf[2 * i + 1];
    s[threadIdx.x] = acc;
    __syncthreads();
    for (int o = 128; o; o >>= 1) {
        if (threadIdx.x < o) s[threadIdx.x] |= s[threadIdx.x + o];
        __syncthreads();
    }
    if (threadIdx.x == 0) g_is64 = (s[0] == 0) ? 1 : 0;
}

__global__ void k_convert(const void* __restrict__ ebuf, int twoE) {
    int i = blockIdx.x * blockDim.x + threadIdx.x;
    if (i >= twoE) return;
    int v;
    if (g_is64) v = (int)((const long long*)ebuf)[i];
    else        v = ((const int*)ebuf)[i];
    g_idx[i] = v;
}

// ---------------- degree / norm ----------------
__global__ void k_deg_init(int n) {
    int i = blockIdx.x * blockDim.x + threadIdx.x;
    if (i < n) g_deg[i] = 1;  // self loop
}

__global__ void k_deg_count(const int* __restrict__ dst, int E, int n) {
    int e = blockIdx.x * blockDim.x + threadIdx.x;
    if (e < E) {
        int d = dst[e];
        if ((unsigned)d < (unsigned)n) atomicAdd(&g_deg[d], 1);
    }
}

__global__ void k_dis(int n) {
    int i = blockIdx.x * blockDim.x + threadIdx.x;
    if (i < n) g_dis[i] = rsqrtf((float)g_deg[i]);
}

// ---------------- GEMM: [n,K] @ [K,64] -> [n,64] ----------------
template <int K>
__global__ void __launch_bounds__(256) k_gemm64(const float* __restrict__ X,
                                                const float* __restrict__ W,
                                                float* __restrict__ out, int n) {
    extern __shared__ float smem[];
    float* sW = smem;                 // K*64
    float* sX = smem + K * 64;        // 64*(K+1) padded
    const int tid = threadIdx.x;
    const int rowBase = blockIdx.x * 64;

    for (int i = tid; i < K * 16; i += 256)
        ((float4*)sW)[i] = ((const float4*)W)[i];

    for (int i = tid; i < 64 * (K / 4); i += 256) {
        int idx = i * 4;
        int r = idx / K, c = idx - r * K;
        float4 v = make_float4(0.f, 0.f, 0.f, 0.f);
        if (rowBase + r < n)
            v = *(const float4*)(X + (size_t)(rowBase + r) * K + c);
        float* p = sX + r * (K + 1) + c;
        p[0] = v.x; p[1] = v.y; p[2] = v.z; p[3] = v.w;
    }
    __syncthreads();

    const int tx = tid & 15;
    const int ty = tid >> 4;
    float acc[4][4] = {};

#pragma unroll 16
    for (int k = 0; k < K; k++) {
        float4 wv = *(const float4*)(sW + k * 64 + tx * 4);
#pragma unroll
        for (int r = 0; r < 4; r++) {
            float xv = sX[(ty * 4 + r) * (K + 1) + k];
            acc[r][0] += xv * wv.x;
            acc[r][1] += xv * wv.y;
            acc[r][2] += xv * wv.z;
            acc[r][3] += xv * wv.w;
        }
    }

#pragma unroll
    for (int r = 0; r < 4; r++) {
        int row = rowBase + ty * 4 + r;
        if (row < n)
            *(float4*)(out + (size_t)row * 64 + tx * 4) =
                make_float4(acc[r][0], acc[r][1], acc[r][2], acc[r][3]);
    }
}

// ---------------- aggregation (F=64) ----------------
__global__ void k_self_init(const float* __restrict__ h, float* __restrict__ a, int n16) {
    int i = blockIdx.x * blockDim.x + threadIdx.x;
    if (i >= n16) return;
    float d = g_dis[i >> 4];
    d *= d;
    float4 v = ((const float4*)h)[i];
    v.x *= d; v.y *= d; v.z *= d; v.w *= d;
    ((float4*)a)[i] = v;
}

// a[dst] += h[src] * dis[src]*dis[dst]   (16 threads per edge, float4 atomics)
__global__ void k_scatter64(const int* __restrict__ src, const int* __restrict__ dst,
                            const float* __restrict__ h,
                            float* __restrict__ a, int E, int n) {
    int t = blockIdx.x * blockDim.x + threadIdx.x;
    int e = t >> 4;
    if (e >= E) return;
    int c = (t & 15) * 4;
    int s = src[e];
    int d = dst[e];
    if ((unsigned)s >= (unsigned)n || (unsigned)d >= (unsigned)n) return;
    float nrm = g_dis[s] * g_dis[d];
    float4 hv = *(const float4*)(h + (size_t)s * 64 + c);
    float4 m = make_float4(hv.x * nrm, hv.y * nrm, hv.z * nrm, hv.w * nrm);
    atomicAdd((float4*)(a + (size_t)d * 64 + c), m);
}

__global__ void k_bias_relu(const float* __restrict__ a, const float* __restrict__ b,
                            float* __restrict__ h, int n16) {
    int i = blockIdx.x * blockDim.x + threadIdx.x;
    if (i >= n16) return;
    float4 v = ((const float4*)a)[i];
    float4 bb = ((const float4*)b)[i & 15];
    v.x = fmaxf(v.x + bb.x, 0.f);
    v.y = fmaxf(v.y + bb.y, 0.f);
    v.z = fmaxf(v.z + bb.z, 0.f);
    v.w = fmaxf(v.w + bb.w, 0.f);
    ((float4*)h)[i] = v;
}

// ---------------- layer 3 ----------------
__global__ void k_gemv64(const float* __restrict__ h, const float* __restrict__ w,
                         float* __restrict__ t, int n) {
    int warp = (blockIdx.x * blockDim.x + threadIdx.x) >> 5;
    int lane = threadIdx.x & 31;
    if (warp >= n) return;
    const float* row = h + (size_t)warp * 64;
    float v = row[lane] * __ldg(w + lane) + row[lane + 32] * __ldg(w + lane + 32);
#pragma unroll
    for (int o = 16; o; o >>= 1) v += __shfl_down_sync(0xffffffffu, v, o);
    if (lane == 0) t[warp] = v;
}

__global__ void k_self1(const float* __restrict__ t, float* __restrict__ out, int n) {
    int i = blockIdx.x * blockDim.x + threadIdx.x;
    if (i >= n) return;
    float d = g_dis[i];
    out[i] = t[i] * d * d;
}

__global__ void k_scatter1(const int* __restrict__ src, const int* __restrict__ dst,
                           const float* __restrict__ t,
                           float* __restrict__ out, int E, int n) {
    int e = blockIdx.x * blockDim.x + threadIdx.x;
    if (e >= E) return;
    int s = src[e];
    int d = dst[e];
    if ((unsigned)s >= (unsigned)n || (unsigned)d >= (unsigned)n) return;
    atomicAdd(out + d, t[s] * g_dis[s] * g_dis[d]);
}

__global__ void k_sigmoid(float* __restrict__ out, const float* __restrict__ b3, int n) {
    int i = blockIdx.x * blockDim.x + threadIdx.x;
    if (i >= n) return;
    float z = out[i] + __ldg(b3);
    out[i] = 1.f / (1.f + expf(-z));
}

// ---------------- launcher ----------------
extern "C" void kernel_launch(void* const* d_in, const int* in_sizes, int n_in,
                              void* d_out, int out_size) {
    // --- size-based input identification (robust to metadata ordering) ---
    int ix = -1, iei = -1, iW1 = -1, iW2 = -1, ib3 = -1;
    int i64s[3] = {-1, -1, -1};
    int n64 = 0;
    // x is the largest float tensor; edge_index is 2E elements.
    // Find the two largest by element count.
    {
        int big0 = -1, big1 = -1;
        for (int i = 0; i < n_in; i++) {
            if (big0 < 0 || in_sizes[i] > in_sizes[big0]) { big1 = big0; big0 = i; }
            else if (big1 < 0 || in_sizes[i] > in_sizes[big1]) { big1 = i; }
        }
        ix = big0; iei = big1;  // x (N*128) > edge (2E) for these shapes
    }
    for (int i = 0; i < n_in; i++) {
        if (i == ix || i == iei) continue;
        int s = in_sizes[i];
        if (s == 128 * 64) iW1 = i;
        else if (s == 64 * 64) iW2 = i;
        else if (s == 1) ib3 = i;
        else if (s == 64 && n64 < 3) i64s[n64++] = i;
    }
    int ib1, ib2, iW3;
    if (i64s[0] > iW2) { iW3 = i64s[0]; ib1 = i64s[1]; ib2 = i64s[2]; }  // alphabetical-ish
    else               { ib1 = i64s[0]; ib2 = i64s[1]; iW3 = i64s[2]; }  // insertion order

    const float* x   = (const float*)d_in[ix];
    const float* W1  = (const float*)d_in[iW1];
    const float* b1  = (const float*)d_in[ib1];
    const float* W2  = (const float*)d_in[iW2];
    const float* b2  = (const float*)d_in[ib2];
    const float* W3  = (const float*)d_in[iW3];
    const float* b3  = (const float*)d_in[ib3];
    const void*  ebuf = d_in[iei];

    const int n = in_sizes[ix] / 128;
    const int E = in_sizes[iei] / 2;
    float* out = (float*)d_out;

    float* hbuf; cudaGetSymbolAddress((void**)&hbuf, g_h);
    float* abuf; cudaGetSymbolAddress((void**)&abuf, g_a);
    float* tbuf; cudaGetSymbolAddress((void**)&tbuf, g_t);
    int* idxbuf; cudaGetSymbolAddress((void**)&idxbuf, g_idx);
    const int* srcI = idxbuf;
    const int* dstI = idxbuf + E;

    const int TB = 256;
    const int nBlocks  = (n + TB - 1) / TB;
    const int eBlocks  = (E + TB - 1) / TB;
    const int twoE     = 2 * E;
    const int cvtBlk   = (twoE + TB - 1) / TB;
    const int n16      = n * 16;
    const int n16Blk   = (n16 + TB - 1) / TB;
    const int e16Blk   = ((E * 16) + TB - 1) / TB;
    const int gemmBlk  = (n + 63) / 64;
    const int gemvBlk  = ((n * 32) + TB - 1) / TB;

    const int smem128 = (128 * 64 + 64 * 129) * (int)sizeof(float);
    const int smem64  = (64 * 64 + 64 * 65) * (int)sizeof(float);
    cudaFuncSetAttribute(k_gemm64<128>, cudaFuncAttributeMaxDynamicSharedMemorySize, smem128);
    cudaFuncSetAttribute(k_gemm64<64>,  cudaFuncAttributeMaxDynamicSharedMemorySize, smem64);

    // normalize edge indices (dtype-agnostic)
    k_detect<<<1, TB>>>((const unsigned*)ebuf, 4096);
    k_convert<<<cvtBlk, TB>>>(ebuf, twoE);

    // norm
    k_deg_init<<<nBlocks, TB>>>(n);
    k_deg_count<<<eBlocks, TB>>>(dstI, E, n);
    k_dis<<<nBlocks, TB>>>(n);

    // layer 1: h = x @ W1 ; a = Agg(h) ; h = relu(a + b1)
    k_gemm64<128><<<gemmBlk, TB, smem128>>>(x, W1, hbuf, n);
    k_self_init<<<n16Blk, TB>>>(hbuf, abuf, n16);
    k_scatter64<<<e16Blk, TB>>>(srcI, dstI, hbuf, abuf, E, n);
    k_bias_relu<<<n16Blk, TB>>>(abuf, b1, hbuf, n16);

    // layer 2
    k_gemm64<64><<<gemmBlk, TB, smem64>>>(hbuf, W2, abuf, n);
    k_self_init<<<n16Blk, TB>>>(abuf, hbuf, n16);
    k_scatter64<<<e16Blk, TB>>>(srcI, dstI, abuf, hbuf, E, n);
    k_bias_relu<<<n16Blk, TB>>>(hbuf, b2, abuf, n16);

    // layer 3: project to scalar FIRST, then aggregate at F=1
    k_gemv64<<<gemvBlk, TB>>>(abuf, W3, tbuf, n);
    k_self1<<<nBlocks, TB>>>(tbuf, out, n);
    k_scatter1<<<eBlocks, TB>>>(srcI, dstI, tbuf, out, E, n);
    k_sigmoid<<<nBlocks, TB>>>(out, b3, n);
}

// round 3
// speedup vs baseline: 1.3654x; 1.3654x over previous
#include <cuda_runtime.h>
#include <cuda_bf16.h>
#include <math.h>

#define NN 100000
#define EE 1600000

// Scratch (device globals: allocation-free rule)
__device__ float g_h[(size_t)NN * 64];
__device__ float g_a[(size_t)NN * 64];
__device__ float g_t[NN];
__device__ int   g_cnt[NN];                 // in-degree (edges only)
__device__ float g_dis[NN];
__device__ int   g_idx[(size_t)2 * EE];     // normalized int32 edge indices
__device__ int   g_is64;
__device__ int   g_rowptr[NN + 1];
__device__ int   g_cursor[NN];
__device__ int   g_esrc[EE];                // CSR: src per (dst-grouped) edge
__device__ float g_ew[EE];                  // CSR: norm per edge
__device__ int   g_bsum[1024];              // scan partials
__device__ int   g_boff[1024];

// ---------------- edge dtype detection + normalization ----------------
__global__ void k_detect(const unsigned* __restrict__ buf, int nwords) {
    __shared__ unsigned s[256];
    unsigned acc = 0;
    for (int i = threadIdx.x; i < nwords; i += 256) acc |= buf[2 * i + 1];
    s[threadIdx.x] = acc;
    __syncthreads();
    for (int o = 128; o; o >>= 1) {
        if (threadIdx.x < o) s[threadIdx.x] |= s[threadIdx.x + o];
        __syncthreads();
    }
    if (threadIdx.x == 0) g_is64 = (s[0] == 0) ? 1 : 0;
}

__global__ void k_convert(const void* __restrict__ ebuf, int twoE) {
    int i = blockIdx.x * blockDim.x + threadIdx.x;
    if (i >= twoE) return;
    g_idx[i] = g_is64 ? (int)((const long long*)ebuf)[i] : ((const int*)ebuf)[i];
}

// ---------------- degree / norm ----------------
__global__ void k_cnt_init(int n) {
    int i = blockIdx.x * blockDim.x + threadIdx.x;
    if (i < n) g_cnt[i] = 0;
}

__global__ void k_deg_count(const int* __restrict__ dst, int E, int n) {
    int e = blockIdx.x * blockDim.x + threadIdx.x;
    if (e < E) {
        int d = dst[e];
        if ((unsigned)d < (unsigned)n) atomicAdd(&g_cnt[d], 1);
    }
}

__global__ void k_dis(int n) {
    int i = blockIdx.x * blockDim.x + threadIdx.x;
    if (i < n) g_dis[i] = rsqrtf((float)(g_cnt[i] + 1));  // +1 self loop
}

// ---------------- exclusive scan of g_cnt -> g_rowptr ----------------
#define SCB 1024
__global__ void k_scan1(int n) {
    __shared__ int s[SCB];
    int tid = threadIdx.x;
    int i = blockIdx.x * SCB + tid;
    int v = (i < n) ? g_cnt[i] : 0;
    s[tid] = v;
    __syncthreads();
    for (int o = 1; o < SCB; o <<= 1) {
        int t = (tid >= o) ? s[tid - o] : 0;
        __syncthreads();
        s[tid] += t;
        __syncthreads();
    }
    if (i < n) g_rowptr[i] = s[tid] - v;  // exclusive
    if (tid == SCB - 1) g_bsum[blockIdx.x] = s[tid];
}

__global__ void k_scan2(int nb) {
    __shared__ int s[SCB];
    int tid = threadIdx.x;
    int v = (tid < nb) ? g_bsum[tid] : 0;
    s[tid] = v;
    __syncthreads();
    for (int o = 1; o < SCB; o <<= 1) {
        int t = (tid >= o) ? s[tid - o] : 0;
        __syncthreads();
        s[tid] += t;
        __syncthreads();
    }
    if (tid < nb) g_boff[tid] = s[tid] - v;  // exclusive block offsets
}

__global__ void k_scan3(int n, int E) {
    int i = blockIdx.x * blockDim.x + threadIdx.x;
    if (i < n) {
        int r = g_rowptr[i] + g_boff[i >> 10];
        g_rowptr[i] = r;
        g_cursor[i] = r;
    }
    if (i == 0) g_rowptr[n] = E;
}

// ---------------- CSR fill: (src, norm) grouped by dst ----------------
__global__ void k_fill(const int* __restrict__ src, const int* __restrict__ dst,
                       int E, int n) {
    int e = blockIdx.x * blockDim.x + threadIdx.x;
    if (e >= E) return;
    int s = src[e], d = dst[e];
    if ((unsigned)s >= (unsigned)n || (unsigned)d >= (unsigned)n) return;
    int pos = atomicAdd(&g_cursor[d], 1);
    g_esrc[pos] = s;
    g_ew[pos] = g_dis[s] * g_dis[d];
}

// ---------------- GEMM: [n,K] @ [K,64] -> [n,64] ----------------
template <int K>
__global__ void __launch_bounds__(256) k_gemm64(const float* __restrict__ X,
                                                const float* __restrict__ W,
                                                float* __restrict__ out, int n) {
    extern __shared__ float smem[];
    float* sW = smem;              // K*64
    float* sX = smem + K * 64;     // 64*(K+1)
    const int tid = threadIdx.x;
    const int rowBase = blockIdx.x * 64;

    for (int i = tid; i < K * 16; i += 256)
        ((float4*)sW)[i] = ((const float4*)W)[i];

    for (int i = tid; i < 64 * (K / 4); i += 256) {
        int idx = i * 4;
        int r = idx / K, c = idx - r * K;
        float4 v = make_float4(0.f, 0.f, 0.f, 0.f);
        if (rowBase + r < n)
            v = *(const float4*)(X + (size_t)(rowBase + r) * K + c);
        float* p = sX + r * (K + 1) + c;
        p[0] = v.x; p[1] = v.y; p[2] = v.z; p[3] = v.w;
    }
    __syncthreads();

    const int tx = tid & 15;
    const int ty = tid >> 4;
    float acc[4][4] = {};

#pragma unroll 16
    for (int k = 0; k < K; k++) {
        float4 wv = *(const float4*)(sW + k * 64 + tx * 4);
#pragma unroll
        for (int r = 0; r < 4; r++) {
            float xv = sX[(ty * 4 + r) * (K + 1) + k];
            acc[r][0] += xv * wv.x;
            acc[r][1] += xv * wv.y;
            acc[r][2] += xv * wv.z;
            acc[r][3] += xv * wv.w;
        }
    }

#pragma unroll
    for (int r = 0; r < 4; r++) {
        int row = rowBase + ty * 4 + r;
        if (row < n)
            *(float4*)(out + (size_t)row * 64 + tx * 4) =
                make_float4(acc[r][0], acc[r][1], acc[r][2], acc[r][3]);
    }
}

// ---------------- fused CSR aggregation (F=64): warp per node ----------------
// out[i] = relu?( sum_{j in N(i)} h[src_j]*w_j + h[i]*dis_i^2 + b )
template <bool RELU>
__global__ void __launch_bounds__(256) k_gather64(const float* __restrict__ h,
                                                  const float* __restrict__ b,
                                                  float* __restrict__ out, int n) {
    int node = (blockIdx.x * blockDim.x + threadIdx.x) >> 5;
    int lane = threadIdx.x & 31;
    if (node >= n) return;
    float dis = g_dis[node];
    float selfw = dis * dis;
    const float* hr = h + (size_t)node * 64;
    float a0 = hr[lane] * selfw;
    float a1 = hr[lane + 32] * selfw;
    int beg = g_rowptr[node], end = g_rowptr[node + 1];
    for (int base = beg; base < end; base += 32) {
        int m = min(32, end - base);
        int s = 0; float w = 0.f;
        if (lane < m) { s = g_esrc[base + lane]; w = g_ew[base + lane]; }
#pragma unroll 4
        for (int k = 0; k < m; k++) {
            int   sk = __shfl_sync(0xffffffffu, s, k);
            float wk = __shfl_sync(0xffffffffu, w, k);
            const float* hs = h + (size_t)sk * 64;
            a0 = fmaf(hs[lane], wk, a0);
            a1 = fmaf(hs[lane + 32], wk, a1);
        }
    }
    a0 += __ldg(b + lane);
    a1 += __ldg(b + lane + 32);
    if (RELU) { a0 = fmaxf(a0, 0.f); a1 = fmaxf(a1, 0.f); }
    out[(size_t)node * 64 + lane] = a0;
    out[(size_t)node * 64 + lane + 32] = a1;
}

// ---------------- layer 3 ----------------
__global__ void k_gemv64(const float* __restrict__ h, const float* __restrict__ w,
                         float* __restrict__ t, int n) {
    int warp = (blockIdx.x * blockDim.x + threadIdx.x) >> 5;
    int lane = threadIdx.x & 31;
    if (warp >= n) return;
    const float* row = h + (size_t)warp * 64;
    float v = row[lane] * __ldg(w + lane) + row[lane + 32] * __ldg(w + lane + 32);
#pragma unroll
    for (int o = 16; o; o >>= 1) v += __shfl_down_sync(0xffffffffu, v, o);
    if (lane == 0) t[warp] = v;
}

// out[i] = sigmoid( agg1(t)[i] + b3 )
__global__ void k_out1(const float* __restrict__ t, const float* __restrict__ b3,
                       float* __restrict__ out, int n) {
    int i = blockIdx.x * blockDim.x + threadIdx.x;
    if (i >= n) return;
    float dis = g_dis[i];
    float z = t[i] * dis * dis;
    int beg = g_rowptr[i], end = g_rowptr[i + 1];
    for (int j = beg; j < end; j++)
        z = fmaf(t[g_esrc[j]], g_ew[j], z);
    z += __ldg(b3);
    out[i] = 1.f / (1.f + expf(-z));
}

// ---------------- launcher ----------------
extern "C" void kernel_launch(void* const* d_in, const int* in_sizes, int n_in,
                              void* d_out, int out_size) {
    // size-based input identification (robust to metadata ordering)
    int ix = -1, iei = -1, iW1 = -1, iW2 = -1, ib3 = -1;
    int i64s[3] = {-1, -1, -1};
    int n64 = 0;
    {
        int big0 = -1, big1 = -1;
        for (int i = 0; i < n_in; i++) {
            if (big0 < 0 || in_sizes[i] > in_sizes[big0]) { big1 = big0; big0 = i; }
            else if (big1 < 0 || in_sizes[i] > in_sizes[big1]) { big1 = i; }
        }
        ix = big0; iei = big1;
    }
    for (int i = 0; i < n_in; i++) {
        if (i == ix || i == iei) continue;
        int s = in_sizes[i];
        if (s == 128 * 64) iW1 = i;
        else if (s == 64 * 64) iW2 = i;
        else if (s == 1) ib3 = i;
        else if (s == 64 && n64 < 3) i64s[n64++] = i;
    }
    int ib1, ib2, iW3;
    if (i64s[0] > iW2) { iW3 = i64s[0]; ib1 = i64s[1]; ib2 = i64s[2]; }
    else               { ib1 = i64s[0]; ib2 = i64s[1]; iW3 = i64s[2]; }

    const float* x   = (const float*)d_in[ix];
    const float* W1  = (const float*)d_in[iW1];
    const float* b1  = (const float*)d_in[ib1];
    const float* W2  = (const float*)d_in[iW2];
    const float* b2  = (const float*)d_in[ib2];
    const float* W3  = (const float*)d_in[iW3];
    const float* b3  = (const float*)d_in[ib3];
    const void*  ebuf = d_in[iei];

    const int n = in_sizes[ix] / 128;
    const int E = in_sizes[iei] / 2;
    float* out = (float*)d_out;

    float* hbuf; cudaGetSymbolAddress((void**)&hbuf, g_h);
    float* abuf; cudaGetSymbolAddress((void**)&abuf, g_a);
    float* tbuf; cudaGetSymbolAddress((void**)&tbuf, g_t);
    int* idxbuf; cudaGetSymbolAddress((void**)&idxbuf, g_idx);
    const int* srcI = idxbuf;
    const int* dstI = idxbuf + E;

    const int TB = 256;
    const int nBlocks = (n + TB - 1) / TB;
    const int eBlocks = (E + TB - 1) / TB;
    const int twoE    = 2 * E;
    const int cvtBlk  = (twoE + TB - 1) / TB;
    const int gemmBlk = (n + 63) / 64;
    const int warpBlk = ((n * 32) + TB - 1) / TB;  // warp-per-node grids
    const int nb      = (n + SCB - 1) / SCB;

    const int smem128 = (128 * 64 + 64 * 129) * (int)sizeof(float);
    const int smem64  = (64 * 64 + 64 * 65) * (int)sizeof(float);
    cudaFuncSetAttribute(k_gemm64<128>, cudaFuncAttributeMaxDynamicSharedMemorySize, smem128);
    cudaFuncSetAttribute(k_gemm64<64>,  cudaFuncAttributeMaxDynamicSharedMemorySize, smem64);

    // edge normalization + norm + CSR build
    k_detect<<<1, TB>>>((const unsigned*)ebuf, 4096);
    k_convert<<<cvtBlk, TB>>>(ebuf, twoE);
    k_cnt_init<<<nBlocks, TB>>>(n);
    k_deg_count<<<eBlocks, TB>>>(dstI, E, n);
    k_dis<<<nBlocks, TB>>>(n);
    k_scan1<<<nb, SCB>>>(n);
    k_scan2<<<1, SCB>>>(nb);
    k_scan3<<<nBlocks, TB>>>(n, E);
    k_fill<<<eBlocks, TB>>>(srcI, dstI, E, n);

    // layer 1
    k_gemm64<128><<<gemmBlk, TB, smem128>>>(x, W1, hbuf, n);
    k_gather64<true><<<warpBlk, TB>>>(hbuf, b1, abuf, n);

    // layer 2
    k_gemm64<64><<<gemmBlk, TB, smem64>>>(abuf, W2, hbuf, n);
    k_gather64<true><<<warpBlk, TB>>>(hbuf, b2, abuf, n);

    // layer 3: project to scalar, aggregate at F=1, sigmoid
    k_gemv64<<<warpBlk, TB>>>(abuf, W3, tbuf, n);
    k_out1<<<nBlocks, TB>>>(tbuf, b3, out, n);
}

// round 4
// speedup vs baseline: 1.4491x; 1.0613x over previous
#include <cuda_runtime.h>
#include <cuda_fp16.h>
#include <math.h>

#define NN 100000
#define EE 1600000

// Scratch (device globals: allocation-free rule)
__device__ __half g_h16[(size_t)NN * 64];   // gemm output (fp16, gather input)
__device__ float  g_a[(size_t)NN * 64];     // aggregation output (fp32)
__device__ float  g_t[NN];                  // layer-3 projected scalar
__device__ int    g_cnt[NN];
__device__ float  g_dis[NN];
__device__ int    g_idx[(size_t)2 * EE];    // normalized int32 edge indices
__device__ int    g_is64;
__device__ int    g_rowptr[NN + 1];
__device__ int    g_cursor[NN];
__device__ int2   g_epack[EE];              // CSR: {src, weight-as-int} per edge
__device__ int    g_bsum[1024];
__device__ int    g_boff[1024];

// ---------------- edge dtype detection ----------------
__global__ void k_detect(const unsigned* __restrict__ buf, int nwords) {
    __shared__ unsigned s[256];
    unsigned acc = 0;
    for (int i = threadIdx.x; i < nwords; i += 256) acc |= buf[2 * i + 1];
    s[threadIdx.x] = acc;
    __syncthreads();
    for (int o = 128; o; o >>= 1) {
        if (threadIdx.x < o) s[threadIdx.x] |= s[threadIdx.x + o];
        __syncthreads();
    }
    if (threadIdx.x == 0) g_is64 = (s[0] == 0) ? 1 : 0;
}

__global__ void k_cnt_init(int n) {
    int i = blockIdx.x * blockDim.x + threadIdx.x;
    if (i < n) g_cnt[i] = 0;
}

// convert + degree count in one pass
__global__ void k_prep(const void* __restrict__ ebuf, int E, int n) {
    int e = blockIdx.x * blockDim.x + threadIdx.x;
    if (e >= E) return;
    int s, d;
    if (g_is64) {
        s = (int)((const long long*)ebuf)[e];
        d = (int)((const long long*)ebuf)[(size_t)E + e];
    } else {
        s = ((const int*)ebuf)[e];
        d = ((const int*)ebuf)[(size_t)E + e];
    }
    g_idx[e] = s;
    g_idx[(size_t)E + e] = d;
    if ((unsigned)d < (unsigned)n) atomicAdd(&g_cnt[d], 1);
}

// ---------------- exclusive scan of g_cnt -> g_rowptr (+ dis) ----------------
#define SCB 1024
__global__ void k_scan1(int n) {
    __shared__ int s[SCB];
    int tid = threadIdx.x;
    int i = blockIdx.x * SCB + tid;
    int v = (i < n) ? g_cnt[i] : 0;
    if (i < n) g_dis[i] = rsqrtf((float)(v + 1));  // +1 self loop
    s[tid] = v;
    __syncthreads();
    for (int o = 1; o < SCB; o <<= 1) {
        int t = (tid >= o) ? s[tid - o] : 0;
        __syncthreads();
        s[tid] += t;
        __syncthreads();
    }
    if (i < n) g_rowptr[i] = s[tid] - v;
    if (tid == SCB - 1) g_bsum[blockIdx.x] = s[tid];
}

__global__ void k_scan2(int nb) {
    __shared__ int s[SCB];
    int tid = threadIdx.x;
    int v = (tid < nb) ? g_bsum[tid] : 0;
    s[tid] = v;
    __syncthreads();
    for (int o = 1; o < SCB; o <<= 1) {
        int t = (tid >= o) ? s[tid - o] : 0;
        __syncthreads();
        s[tid] += t;
        __syncthreads();
    }
    if (tid < nb) g_boff[tid] = s[tid] - v;
}

__global__ void k_scan3(int n, int E) {
    int i = blockIdx.x * blockDim.x + threadIdx.x;
    if (i < n) {
        int r = g_rowptr[i] + g_boff[i >> 10];
        g_rowptr[i] = r;
        g_cursor[i] = r;
    }
    if (i == 0) g_rowptr[n] = E;
}

// ---------------- CSR fill ----------------
__global__ void k_fill(const int* __restrict__ src, const int* __restrict__ dst,
                       int E, int n) {
    int e = blockIdx.x * blockDim.x + threadIdx.x;
    if (e >= E) return;
    int s = src[e], d = dst[e];
    if ((unsigned)s >= (unsigned)n || (unsigned)d >= (unsigned)n) return;
    int pos = atomicAdd(&g_cursor[d], 1);
    float w = g_dis[s] * g_dis[d];
    g_epack[pos] = make_int2(s, __float_as_int(w));
}

// ---------------- GEMM: [n,K]fp32 @ [K,64]fp32 -> [n,64]fp16 ----------------
template <int K>
__global__ void __launch_bounds__(256) k_gemm64(const float* __restrict__ X,
                                                const float* __restrict__ W,
                                                __half* __restrict__ out, int n) {
    extern __shared__ float smem[];
    float* sW = smem;              // K*64
    float* sX = smem + K * 64;     // 64*(K+1)
    const int tid = threadIdx.x;
    const int rowBase = blockIdx.x * 64;

    for (int i = tid; i < K * 16; i += 256)
        ((float4*)sW)[i] = ((const float4*)W)[i];

    for (int i = tid; i < 64 * (K / 4); i += 256) {
        int idx = i * 4;
        int r = idx / K, c = idx - r * K;
        float4 v = make_float4(0.f, 0.f, 0.f, 0.f);
        if (rowBase + r < n)
            v = *(const float4*)(X + (size_t)(rowBase + r) * K + c);
        float* p = sX + r * (K + 1) + c;
        p[0] = v.x; p[1] = v.y; p[2] = v.z; p[3] = v.w;
    }
    __syncthreads();

    const int tx = tid & 15;
    const int ty = tid >> 4;
    float acc[4][4] = {};

#pragma unroll 16
    for (int k = 0; k < K; k++) {
        float4 wv = *(const float4*)(sW + k * 64 + tx * 4);
#pragma unroll
        for (int r = 0; r < 4; r++) {
            float xv = sX[(ty * 4 + r) * (K + 1) + k];
            acc[r][0] += xv * wv.x;
            acc[r][1] += xv * wv.y;
            acc[r][2] += xv * wv.z;
            acc[r][3] += xv * wv.w;
        }
    }

#pragma unroll
    for (int r = 0; r < 4; r++) {
        int row = rowBase + ty * 4 + r;
        if (row < n) {
            __half2 h0 = __floats2half2_rn(acc[r][0], acc[r][1]);
            __half2 h1 = __floats2half2_rn(acc[r][2], acc[r][3]);
            uint2 pk = make_uint2(*(unsigned*)&h0, *(unsigned*)&h1);
            ((uint2*)(out + (size_t)row * 64))[tx] = pk;
        }
    }
}

// ---------------- fused CSR aggregation (F=64, fp16 in / fp32 out) ----------------
// out[i] = relu?( sum_j h[src_j]*w_j + h[i]*dis_i^2 + b )
template <bool RELU>
__global__ void __launch_bounds__(256) k_gather64(const __half* __restrict__ h,
                                                  const float* __restrict__ b,
                                                  float* __restrict__ out, int n) {
    int node = (blockIdx.x * blockDim.x + threadIdx.x) >> 5;
    int lane = threadIdx.x & 31;
    if (node >= n) return;
    float dis = g_dis[node];
    float selfw = dis * dis;
    // each lane covers cols {2*lane, 2*lane+1}
    float2 hv = __half22float2(((const __half2*)(h + (size_t)node * 64))[lane]);
    float a0 = hv.x * selfw;
    float a1 = hv.y * selfw;
    int beg = g_rowptr[node], end = g_rowptr[node + 1];
    for (int base = beg; base < end; base += 32) {
        int m = min(32, end - base);
        int2 p = make_int2(0, 0);
        if (lane < m) p = g_epack[base + lane];
#pragma unroll 4
        for (int k = 0; k < m; k++) {
            int   sk = __shfl_sync(0xffffffffu, p.x, k);
            float wk = __int_as_float(__shfl_sync(0xffffffffu, p.y, k));
            float2 hs = __half22float2(((const __half2*)(h + (size_t)sk * 64))[lane]);
            a0 = fmaf(hs.x, wk, a0);
            a1 = fmaf(hs.y, wk, a1);
        }
    }
    float2 bb = ((const float2*)b)[lane];
    a0 += bb.x;
    a1 += bb.y;
    if (RELU) { a0 = fmaxf(a0, 0.f); a1 = fmaxf(a1, 0.f); }
    ((float2*)(out + (size_t)node * 64))[lane] = make_float2(a0, a1);
}

// ---------------- layer 3 ----------------
__global__ void k_gemv64(const float* __restrict__ h, const float* __restrict__ w,
                         float* __restrict__ t, int n) {
    int warp = (blockIdx.x * blockDim.x + threadIdx.x) >> 5;
    int lane = threadIdx.x & 31;
    if (warp >= n) return;
    const float* row = h + (size_t)warp * 64;
    float v = row[lane] * __ldg(w + lane) + row[lane + 32] * __ldg(w + lane + 32);
#pragma unroll
    for (int o = 16; o; o >>= 1) v += __shfl_down_sync(0xffffffffu, v, o);
    if (lane == 0) t[warp] = v;
}

__global__ void k_out1(const float* __restrict__ t, const float* __restrict__ b3,
                       float* __restrict__ out, int n) {
    int i = blockIdx.x * blockDim.x + threadIdx.x;
    if (i >= n) return;
    float dis = g_dis[i];
    float z = t[i] * dis * dis;
    int beg = g_rowptr[i], end = g_rowptr[i + 1];
    for (int j = beg; j < end; j++) {
        int2 p = g_epack[j];
        z = fmaf(t[p.x], __int_as_float(p.y), z);
    }
    z += __ldg(b3);
    out[i] = 1.f / (1.f + expf(-z));
}

// ---------------- launcher ----------------
extern "C" void kernel_launch(void* const* d_in, const int* in_sizes, int n_in,
                              void* d_out, int out_size) {
    // size-based input identification (robust to metadata ordering)
    int ix = -1, iei = -1, iW1 = -1, iW2 = -1, ib3 = -1;
    int i64s[3] = {-1, -1, -1};
    int n64 = 0;
    {
        int big0 = -1, big1 = -1;
        for (int i = 0; i < n_in; i++) {
            if (big0 < 0 || in_sizes[i] > in_sizes[big0]) { big1 = big0; big0 = i; }
            else if (big1 < 0 || in_sizes[i] > in_sizes[big1]) { big1 = i; }
        }
        ix = big0; iei = big1;
    }
    for (int i = 0; i < n_in; i++) {
        if (i == ix || i == iei) continue;
        int s = in_sizes[i];
        if (s == 128 * 64) iW1 = i;
        else if (s == 64 * 64) iW2 = i;
        else if (s == 1) ib3 = i;
        else if (s == 64 && n64 < 3) i64s[n64++] = i;
    }
    int ib1, ib2, iW3;
    if (i64s[0] > iW2) { iW3 = i64s[0]; ib1 = i64s[1]; ib2 = i64s[2]; }
    else               { ib1 = i64s[0]; ib2 = i64s[1]; iW3 = i64s[2]; }

    const float* x   = (const float*)d_in[ix];
    const float* W1  = (const float*)d_in[iW1];
    const float* b1  = (const float*)d_in[ib1];
    const float* W2  = (const float*)d_in[iW2];
    const float* b2  = (const float*)d_in[ib2];
    const float* W3  = (const float*)d_in[iW3];
    const float* b3  = (const float*)d_in[ib3];
    const void*  ebuf = d_in[iei];

    const int n = in_sizes[ix] / 128;
    const int E = in_sizes[iei] / 2;
    float* out = (float*)d_out;

    __half* hbuf; cudaGetSymbolAddress((void**)&hbuf, g_h16);
    float*  abuf; cudaGetSymbolAddress((void**)&abuf, g_a);
    float*  tbuf; cudaGetSymbolAddress((void**)&tbuf, g_t);
    int* idxbuf;  cudaGetSymbolAddress((void**)&idxbuf, g_idx);
    const int* srcI = idxbuf;
    const int* dstI = idxbuf + E;

    const int TB = 256;
    const int nBlocks = (n + TB - 1) / TB;
    const int eBlocks = (E + TB - 1) / TB;
    const int gemmBlk = (n + 63) / 64;
    const int warpBlk = ((n * 32) + TB - 1) / TB;
    const int nb      = (n + SCB - 1) / SCB;

    const int smem128 = (128 * 64 + 64 * 129) * (int)sizeof(float);
    const int smem64  = (64 * 64 + 64 * 65) * (int)sizeof(float);
    cudaFuncSetAttribute(k_gemm64<128>, cudaFuncAttributeMaxDynamicSharedMemorySize, smem128);
    cudaFuncSetAttribute(k_gemm64<64>,  cudaFuncAttributeMaxDynamicSharedMemorySize, smem64);

    // preprocessing: dtype detect, convert+count, scan(+dis), CSR fill
    k_detect<<<1, TB>>>((const unsigned*)ebuf, 4096);
    k_cnt_init<<<nBlocks, TB>>>(n);
    k_prep<<<eBlocks, TB>>>(ebuf, E, n);
    k_scan1<<<nb, SCB>>>(n);
    k_scan2<<<1, SCB>>>(nb);
    k_scan3<<<nBlocks, TB>>>(n, E);
    k_fill<<<eBlocks, TB>>>(srcI, dstI, E, n);

    // layer 1
    k_gemm64<128><<<gemmBlk, TB, smem128>>>(x, W1, hbuf, n);
    k_gather64<true><<<warpBlk, TB>>>(hbuf, b1, abuf, n);

    // layer 2
    k_gemm64<64><<<gemmBlk, TB, smem64>>>(abuf, W2, hbuf, n);
    k_gather64<true><<<warpBlk, TB>>>(hbuf, b2, abuf, n);

    // layer 3
    k_gemv64<<<warpBlk, TB>>>(abuf, W3, tbuf, n);
    k_out1<<<nBlocks, TB>>>(tbuf, b3, out, n);
}

// round 5
// speedup vs baseline: 1.8824x; 1.2991x over previous
#include <cuda_runtime.h>
#include <cuda_fp16.h>
#include <math.h>

#define NN 100000
#define EE 1600000

// Scratch (device globals: allocation-free rule)
__device__ __half g_h16[(size_t)NN * 64];   // GEMM output (gather input)
__device__ __half g_a16[(size_t)NN * 64];   // gather output (next GEMM / gemv input)
__device__ float  g_t[NN];                  // layer-3 projected scalar
__device__ int    g_cnt[NN];
__device__ float  g_dis[NN];
__device__ int    g_is64;
__device__ int    g_rowptr[NN + 1];
__device__ int    g_cursor[NN];
__device__ int2   g_epack[EE];              // CSR: {src, weight-as-int} per edge
__device__ int    g_bsum[1024];
__device__ int    g_boff[1024];

// ---------------- edge dtype detection ----------------
__global__ void k_detect(const unsigned* __restrict__ buf, int nwords) {
    __shared__ unsigned s[256];
    unsigned acc = 0;
    for (int i = threadIdx.x; i < nwords; i += 256) acc |= buf[2 * i + 1];
    s[threadIdx.x] = acc;
    __syncthreads();
    for (int o = 128; o; o >>= 1) {
        if (threadIdx.x < o) s[threadIdx.x] |= s[threadIdx.x + o];
        __syncthreads();
    }
    if (threadIdx.x == 0) g_is64 = (s[0] == 0) ? 1 : 0;
}

__global__ void k_cnt_init(int n) {
    int i = blockIdx.x * blockDim.x + threadIdx.x;
    if (i < n) g_cnt[i] = 0;
}

// degree count (reads dst half of raw edge buffer, dtype-agnostic)
__global__ void k_prep(const void* __restrict__ ebuf, int E, int n) {
    int e = blockIdx.x * blockDim.x + threadIdx.x;
    if (e >= E) return;
    int d = g_is64 ? (int)((const long long*)ebuf)[(size_t)E + e]
                   : ((const int*)ebuf)[(size_t)E + e];
    if ((unsigned)d < (unsigned)n) atomicAdd(&g_cnt[d], 1);
}

// ---------------- exclusive scan of g_cnt -> g_rowptr (+ dis) ----------------
#define SCB 1024
__global__ void k_scan1(int n) {
    __shared__ int s[SCB];
    int tid = threadIdx.x;
    int i = blockIdx.x * SCB + tid;
    int v = (i < n) ? g_cnt[i] : 0;
    if (i < n) g_dis[i] = rsqrtf((float)(v + 1));  // +1 self loop
    s[tid] = v;
    __syncthreads();
    for (int o = 1; o < SCB; o <<= 1) {
        int t = (tid >= o) ? s[tid - o] : 0;
        __syncthreads();
        s[tid] += t;
        __syncthreads();
    }
    if (i < n) g_rowptr[i] = s[tid] - v;
    if (tid == SCB - 1) g_bsum[blockIdx.x] = s[tid];
}

__global__ void k_scan2(int nb) {
    __shared__ int s[SCB];
    int tid = threadIdx.x;
    int v = (tid < nb) ? g_bsum[tid] : 0;
    s[tid] = v;
    __syncthreads();
    for (int o = 1; o < SCB; o <<= 1) {
        int t = (tid >= o) ? s[tid - o] : 0;
        __syncthreads();
        s[tid] += t;
        __syncthreads();
    }
    if (tid < nb) g_boff[tid] = s[tid] - v;
}

__global__ void k_scan3(int n, int E) {
    int i = blockIdx.x * blockDim.x + threadIdx.x;
    if (i < n) {
        int r = g_rowptr[i] + g_boff[i >> 10];
        g_rowptr[i] = r;
        g_cursor[i] = r;
    }
    if (i == 0) g_rowptr[n] = E;
}

// ---------------- CSR fill (inline dtype convert) ----------------
__global__ void k_fill(const void* __restrict__ ebuf, int E, int n) {
    int e = blockIdx.x * blockDim.x + threadIdx.x;
    if (e >= E) return;
    int s, d;
    if (g_is64) {
        s = (int)((const long long*)ebuf)[e];
        d = (int)((const long long*)ebuf)[(size_t)E + e];
    } else {
        s = ((const int*)ebuf)[e];
        d = ((const int*)ebuf)[(size_t)E + e];
    }
    if ((unsigned)s >= (unsigned)n || (unsigned)d >= (unsigned)n) return;
    int pos = atomicAdd(&g_cursor[d], 1);
    float w = g_dis[s] * g_dis[d];
    g_epack[pos] = make_int2(s, __float_as_int(w));
}

// ---------------- tensor-core GEMM: [n,K] @ [K,64] -> [n,64]fp16 ----------------
// mma.sync.m16n8k16, fp16 inputs (converted in staging), fp32 accumulate.
// Block: 128 threads = 4 warps, tile 64 rows x 64 cols.
template <int K, bool AHALF>
__global__ void __launch_bounds__(128) k_mma64(const void* __restrict__ Xv,
                                               const float* __restrict__ W,
                                               __half* __restrict__ out, int n) {
    constexpr int PAD = 8;
    constexpr int LDA = K + PAD;
    extern __shared__ __half smem[];
    __half* sA = smem;              // 64 x LDA
    __half* sW = smem + 64 * LDA;   // 64(n) x LDA(k)  — W transposed
    const int tid = threadIdx.x;
    const int rowBase = blockIdx.x * 64;

    // stage A (convert fp32->fp16 if needed)
    if (AHALF) {
        const __half* X = (const __half*)Xv;
        for (int i = tid; i < 64 * K / 8; i += 128) {
            int idx = i * 8;
            int r = idx / K, c = idx - r * K;
            uint4 v = make_uint4(0, 0, 0, 0);
            if (rowBase + r < n) v = *(const uint4*)(X + (size_t)(rowBase + r) * K + c);
            *(uint4*)&sA[r * LDA + c] = v;
        }
    } else {
        const float* X = (const float*)Xv;
        for (int i = tid; i < 64 * K / 4; i += 128) {
            int idx = i * 4;
            int r = idx / K, c = idx - r * K;
            float4 v = make_float4(0.f, 0.f, 0.f, 0.f);
            if (rowBase + r < n) v = *(const float4*)(X + (size_t)(rowBase + r) * K + c);
            *(__half2*)&sA[r * LDA + c] = __floats2half2_rn(v.x, v.y);
            *(__half2*)&sA[r * LDA + c + 2] = __floats2half2_rn(v.z, v.w);
        }
    }
    // stage W transposed: sW[n][k] = W[k][n]
    for (int i = tid; i < K * 64; i += 128) {
        int k = i >> 6, c = i & 63;
        sW[c * LDA + k] = __float2half(W[i]);
    }
    __syncthreads();

    const int wid = tid >> 5, lane = tid & 31;
    const int g = lane >> 2, t2 = (lane & 3) * 2;
    const int aRow = wid * 16;
    float acc[8][4];
#pragma unroll
    for (int j = 0; j < 8; j++) {
        acc[j][0] = acc[j][1] = acc[j][2] = acc[j][3] = 0.f;
    }

#pragma unroll
    for (int kk = 0; kk < K; kk += 16) {
        unsigned a0 = *(const unsigned*)&sA[(aRow + g) * LDA + kk + t2];
        unsigned a1 = *(const unsigned*)&sA[(aRow + g + 8) * LDA + kk + t2];
        unsigned a2 = *(const unsigned*)&sA[(aRow + g) * LDA + kk + t2 + 8];
        unsigned a3 = *(const unsigned*)&sA[(aRow + g + 8) * LDA + kk + t2 + 8];
#pragma unroll
        for (int j = 0; j < 8; j++) {
            unsigned b0 = *(const unsigned*)&sW[(j * 8 + g) * LDA + kk + t2];
            unsigned b1 = *(const unsigned*)&sW[(j * 8 + g) * LDA + kk + t2 + 8];
            asm volatile(
                "mma.sync.aligned.m16n8k16.row.col.f32.f16.f16.f32 "
                "{%0,%1,%2,%3}, {%4,%5,%6,%7}, {%8,%9}, {%0,%1,%2,%3};"
                : "+f"(acc[j][0]), "+f"(acc[j][1]), "+f"(acc[j][2]), "+f"(acc[j][3])
                : "r"(a0), "r"(a1), "r"(a2), "r"(a3), "r"(b0), "r"(b1));
        }
    }

    const int r0 = rowBase + aRow + g;
    const int r1 = r0 + 8;
#pragma unroll
    for (int j = 0; j < 8; j++) {
        int c = j * 8 + t2;
        if (r0 < n)
            *(__half2*)(out + (size_t)r0 * 64 + c) = __floats2half2_rn(acc[j][0], acc[j][1]);
        if (r1 < n)
            *(__half2*)(out + (size_t)r1 * 64 + c) = __floats2half2_rn(acc[j][2], acc[j][3]);
    }
}

// ---------------- fused CSR aggregation (F=64, fp16 in / fp16 out) ----------------
template <bool RELU>
__global__ void __launch_bounds__(256) k_gather64(const __half* __restrict__ h,
                                                  const float* __restrict__ b,
                                                  __half* __restrict__ out, int n) {
    int node = (blockIdx.x * blockDim.x + threadIdx.x) >> 5;
    int lane = threadIdx.x & 31;
    if (node >= n) return;
    float dis = g_dis[node];
    float selfw = dis * dis;
    float2 hv = __half22float2(((const __half2*)(h + (size_t)node * 64))[lane]);
    float a0 = hv.x * selfw;
    float a1 = hv.y * selfw;
    int beg = g_rowptr[node], end = g_rowptr[node + 1];
    for (int base = beg; base < end; base += 32) {
        int m = min(32, end - base);
        int2 p = make_int2(0, 0);
        if (lane < m) p = g_epack[base + lane];
#pragma unroll 4
        for (int k = 0; k < m; k++) {
            int   sk = __shfl_sync(0xffffffffu, p.x, k);
            float wk = __int_as_float(__shfl_sync(0xffffffffu, p.y, k));
            float2 hs = __half22float2(((const __half2*)(h + (size_t)sk * 64))[lane]);
            a0 = fmaf(hs.x, wk, a0);
            a1 = fmaf(hs.y, wk, a1);
        }
    }
    float2 bb = ((const float2*)b)[lane];
    a0 += bb.x;
    a1 += bb.y;
    if (RELU) { a0 = fmaxf(a0, 0.f); a1 = fmaxf(a1, 0.f); }
    ((__half2*)(out + (size_t)node * 64))[lane] = __floats2half2_rn(a0, a1);
}

// ---------------- layer 3 ----------------
__global__ void k_gemv64h(const __half* __restrict__ h, const float* __restrict__ w,
                          float* __restrict__ t, int n) {
    int warp = (blockIdx.x * blockDim.x + threadIdx.x) >> 5;
    int lane = threadIdx.x & 31;
    if (warp >= n) return;
    float2 hv = __half22float2(((const __half2*)(h + (size_t)warp * 64))[lane]);
    float v = hv.x * __ldg(w + 2 * lane) + hv.y * __ldg(w + 2 * lane + 1);
#pragma unroll
    for (int o = 16; o; o >>= 1) v += __shfl_down_sync(0xffffffffu, v, o);
    if (lane == 0) t[warp] = v;
}

__global__ void k_out1(const float* __restrict__ t, const float* __restrict__ b3,
                       float* __restrict__ out, int n) {
    int i = blockIdx.x * blockDim.x + threadIdx.x;
    if (i >= n) return;
    float dis = g_dis[i];
    float z = t[i] * dis * dis;
    int beg = g_rowptr[i], end = g_rowptr[i + 1];
    for (int j = beg; j < end; j++) {
        int2 p = g_epack[j];
        z = fmaf(t[p.x], __int_as_float(p.y), z);
    }
    z += __ldg(b3);
    out[i] = 1.f / (1.f + expf(-z));
}

// ---------------- launcher ----------------
extern "C" void kernel_launch(void* const* d_in, const int* in_sizes, int n_in,
                              void* d_out, int out_size) {
    // size-based input identification (robust to metadata ordering)
    int ix = -1, iei = -1, iW1 = -1, iW2 = -1, ib3 = -1;
    int i64s[3] = {-1, -1, -1};
    int n64 = 0;
    {
        int big0 = -1, big1 = -1;
        for (int i = 0; i < n_in; i++) {
            if (big0 < 0 || in_sizes[i] > in_sizes[big0]) { big1 = big0; big0 = i; }
            else if (big1 < 0 || in_sizes[i] > in_sizes[big1]) { big1 = i; }
        }
        ix = big0; iei = big1;
    }
    for (int i = 0; i < n_in; i++) {
        if (i == ix || i == iei) continue;
        int s = in_sizes[i];
        if (s == 128 * 64) iW1 = i;
        else if (s == 64 * 64) iW2 = i;
        else if (s == 1) ib3 = i;
        else if (s == 64 && n64 < 3) i64s[n64++] = i;
    }
    int ib1, ib2, iW3;
    if (i64s[0] > iW2) { iW3 = i64s[0]; ib1 = i64s[1]; ib2 = i64s[2]; }
    else               { ib1 = i64s[0]; ib2 = i64s[1]; iW3 = i64s[2]; }

    const float* x   = (const float*)d_in[ix];
    const float* W1  = (const float*)d_in[iW1];
    const float* b1  = (const float*)d_in[ib1];
    const float* W2  = (const float*)d_in[iW2];
    const float* b2  = (const float*)d_in[ib2];
    const float* W3  = (const float*)d_in[iW3];
    const float* b3  = (const float*)d_in[ib3];
    const void*  ebuf = d_in[iei];

    const int n = in_sizes[ix] / 128;
    const int E = in_sizes[iei] / 2;
    float* out = (float*)d_out;

    __half* hbuf; cudaGetSymbolAddress((void**)&hbuf, g_h16);
    __half* abuf; cudaGetSymbolAddress((void**)&abuf, g_a16);
    float*  tbuf; cudaGetSymbolAddress((void**)&tbuf, g_t);

    const int TB = 256;
    const int nBlocks = (n + TB - 1) / TB;
    const int eBlocks = (E + TB - 1) / TB;
    const int gemmBlk = (n + 63) / 64;
    const int warpBlk = ((n * 32) + TB - 1) / TB;
    const int nb      = (n + SCB - 1) / SCB;

    const int smem128 = 2 * 64 * (128 + 8) * (int)sizeof(__half);  // 34816
    const int smem64  = 2 * 64 * (64 + 8) * (int)sizeof(__half);   // 18432
    cudaFuncSetAttribute((const void*)k_mma64<128, false>,
                         cudaFuncAttributeMaxDynamicSharedMemorySize, smem128);
    cudaFuncSetAttribute((const void*)k_mma64<64, true>,
                         cudaFuncAttributeMaxDynamicSharedMemorySize, smem64);

    // preprocessing: dtype detect, count, scan(+dis), CSR fill
    k_detect<<<1, TB>>>((const unsigned*)ebuf, 4096);
    k_cnt_init<<<nBlocks, TB>>>(n);
    k_prep<<<eBlocks, TB>>>(ebuf, E, n);
    k_scan1<<<nb, SCB>>>(n);
    k_scan2<<<1, SCB>>>(nb);
    k_scan3<<<nBlocks, TB>>>(n, E);
    k_fill<<<eBlocks, TB>>>(ebuf, E, n);

    // layer 1
    k_mma64<128, false><<<gemmBlk, 128, smem128>>>(x, W1, hbuf, n);
    k_gather64<true><<<warpBlk, TB>>>(hbuf, b1, abuf, n);

    // layer 2
    k_mma64<64, true><<<gemmBlk, 128, smem64>>>(abuf, W2, hbuf, n);
    k_gather64<true><<<warpBlk, TB>>>(hbuf, b2, abuf, n);

    // layer 3
    k_gemv64h<<<warpBlk, TB>>>(abuf, W3, tbuf, n);
    k_out1<<<nBlocks, TB>>>(tbuf, b3, out, n);
}

// round 6
// speedup vs baseline: 1.9635x; 1.0430x over previous
#include <cuda_runtime.h>
#include <cuda_fp16.h>
#include <math.h>

#define NN 100000
#define EE 1600000

// Scratch (device globals: allocation-free rule)
__device__ __half g_h16[(size_t)NN * 64];   // GEMM output (gather input, dis-scaled)
__device__ __half g_a16[(size_t)NN * 64];   // gather output (next GEMM / gemv input)
__device__ float  g_t[NN];                  // layer-3 projected scalar (dis-scaled)
__device__ int    g_cnt[NN];
__device__ float  g_dis[NN];
__device__ int    g_is64;
__device__ int    g_rowptr[NN + 1];
__device__ int    g_cursor[NN];
__device__ int    g_esrc[EE];               // CSR: src per (dst-grouped) edge
__device__ int    g_bsum[1024];
__device__ int    g_boff[1024];

// ---------------- edge dtype detection ----------------
__global__ void k_detect(const unsigned* __restrict__ buf, int nwords) {
    __shared__ unsigned s[256];
    unsigned acc = 0;
    for (int i = threadIdx.x; i < nwords; i += 256) acc |= buf[2 * i + 1];
    s[threadIdx.x] = acc;
    __syncthreads();
    for (int o = 128; o; o >>= 1) {
        if (threadIdx.x < o) s[threadIdx.x] |= s[threadIdx.x + o];
        __syncthreads();
    }
    if (threadIdx.x == 0) g_is64 = (s[0] == 0) ? 1 : 0;
}

// degree count (reads dst half of raw edge buffer, dtype-agnostic)
__global__ void k_prep(const void* __restrict__ ebuf, int E, int n) {
    int e = blockIdx.x * blockDim.x + threadIdx.x;
    if (e >= E) return;
    int d = g_is64 ? (int)((const long long*)ebuf)[(size_t)E + e]
                   : ((const int*)ebuf)[(size_t)E + e];
    if ((unsigned)d < (unsigned)n) atomicAdd(&g_cnt[d], 1);
}

// ---------------- exclusive scan of g_cnt -> g_rowptr (+ dis), warp-shuffle ----------------
__global__ void __launch_bounds__(1024) k_scan1(int n) {
    __shared__ int ws[32];
    int tid = threadIdx.x, lane = tid & 31, w = tid >> 5;
    int i = blockIdx.x * 1024 + tid;
    int v = (i < n) ? g_cnt[i] : 0;
    if (i < n) g_dis[i] = rsqrtf((float)(v + 1));  // +1 self loop
    int inc = v;
#pragma unroll
    for (int o = 1; o < 32; o <<= 1) {
        int t = __shfl_up_sync(0xffffffffu, inc, o);
        if (lane >= o) inc += t;
    }
    if (lane == 31) ws[w] = inc;
    __syncthreads();
    if (w == 0) {
        int b = ws[lane], bi = b;
#pragma unroll
        for (int o = 1; o < 32; o <<= 1) {
            int t = __shfl_up_sync(0xffffffffu, bi, o);
            if (lane >= o) bi += t;
        }
        ws[lane] = bi - b;  // exclusive warp offsets
        if (lane == 31) g_bsum[blockIdx.x] = bi;  // block total
    }
    __syncthreads();
    if (i < n) g_rowptr[i] = ws[w] + inc - v;
}

#define SCB 1024
__global__ void k_scan2(int nb) {
    __shared__ int s[SCB];
    int tid = threadIdx.x;
    int v = (tid < nb) ? g_bsum[tid] : 0;
    s[tid] = v;
    __syncthreads();
    for (int o = 1; o < SCB; o <<= 1) {
        int t = (tid >= o) ? s[tid - o] : 0;
        __syncthreads();
        s[tid] += t;
        __syncthreads();
    }
    if (tid < nb) g_boff[tid] = s[tid] - v;
}

__global__ void k_scan3(int n, int E) {
    int i = blockIdx.x * blockDim.x + threadIdx.x;
    if (i < n) {
        int r = g_rowptr[i] + g_boff[i >> 10];
        g_rowptr[i] = r;
        g_cursor[i] = r;
    }
    if (i == 0) g_rowptr[n] = E;
}

// ---------------- CSR fill: src only (weights factored out) ----------------
__global__ void k_fill(const void* __restrict__ ebuf, int E, int n) {
    int e = blockIdx.x * blockDim.x + threadIdx.x;
    if (e >= E) return;
    int s, d;
    if (g_is64) {
        s = (int)((const long long*)ebuf)[e];
        d = (int)((const long long*)ebuf)[(size_t)E + e];
    } else {
        s = ((const int*)ebuf)[e];
        d = ((const int*)ebuf)[(size_t)E + e];
    }
    if ((unsigned)s >= (unsigned)n || (unsigned)d >= (unsigned)n) return;
    int pos = atomicAdd(&g_cursor[d], 1);
    g_esrc[pos] = s;
}

// ---------------- tensor-core GEMM: [n,K] @ [K,64] -> [n,64]fp16 (opt. dis-scaled) ----------------
template <int K, bool AHALF, bool SCALE>
__global__ void __launch_bounds__(128) k_mma64(const void* __restrict__ Xv,
                                               const float* __restrict__ W,
                                               __half* __restrict__ out, int n) {
    constexpr int PAD = 8;
    constexpr int LDA = K + PAD;
    extern __shared__ __half smem[];
    __half* sA = smem;              // 64 x LDA
    __half* sW = smem + 64 * LDA;   // 64(n) x LDA(k)  — W transposed
    const int tid = threadIdx.x;
    const int rowBase = blockIdx.x * 64;

    if (AHALF) {
        const __half* X = (const __half*)Xv;
        for (int i = tid; i < 64 * K / 8; i += 128) {
            int idx = i * 8;
            int r = idx / K, c = idx - r * K;
            uint4 v = make_uint4(0, 0, 0, 0);
            if (rowBase + r < n) v = *(const uint4*)(X + (size_t)(rowBase + r) * K + c);
            *(uint4*)&sA[r * LDA + c] = v;
        }
    } else {
        const float* X = (const float*)Xv;
        for (int i = tid; i < 64 * K / 4; i += 128) {
            int idx = i * 4;
            int r = idx / K, c = idx - r * K;
            float4 v = make_float4(0.f, 0.f, 0.f, 0.f);
            if (rowBase + r < n) v = *(const float4*)(X + (size_t)(rowBase + r) * K + c);
            *(__half2*)&sA[r * LDA + c] = __floats2half2_rn(v.x, v.y);
            *(__half2*)&sA[r * LDA + c + 2] = __floats2half2_rn(v.z, v.w);
        }
    }
    for (int i = tid; i < K * 64; i += 128) {
        int k = i >> 6, c = i & 63;
        sW[c * LDA + k] = __float2half(W[i]);
    }
    __syncthreads();

    const int wid = tid >> 5, lane = tid & 31;
    const int g = lane >> 2, t2 = (lane & 3) * 2;
    const int aRow = wid * 16;
    float acc[8][4];
#pragma unroll
    for (int j = 0; j < 8; j++)
        acc[j][0] = acc[j][1] = acc[j][2] = acc[j][3] = 0.f;

#pragma unroll
    for (int kk = 0; kk < K; kk += 16) {
        unsigned a0 = *(const unsigned*)&sA[(aRow + g) * LDA + kk + t2];
        unsigned a1 = *(const unsigned*)&sA[(aRow + g + 8) * LDA + kk + t2];
        unsigned a2 = *(const unsigned*)&sA[(aRow + g) * LDA + kk + t2 + 8];
        unsigned a3 = *(const unsigned*)&sA[(aRow + g + 8) * LDA + kk + t2 + 8];
#pragma unroll
        for (int j = 0; j < 8; j++) {
            unsigned b0 = *(const unsigned*)&sW[(j * 8 + g) * LDA + kk + t2];
            unsigned b1 = *(const unsigned*)&sW[(j * 8 + g) * LDA + kk + t2 + 8];
            asm volatile(
                "mma.sync.aligned.m16n8k16.row.col.f32.f16.f16.f32 "
                "{%0,%1,%2,%3}, {%4,%5,%6,%7}, {%8,%9}, {%0,%1,%2,%3};"
                : "+f"(acc[j][0]), "+f"(acc[j][1]), "+f"(acc[j][2]), "+f"(acc[j][3])
                : "r"(a0), "r"(a1), "r"(a2), "r"(a3), "r"(b0), "r"(b1));
        }
    }

    const int r0 = rowBase + aRow + g;
    const int r1 = r0 + 8;
    float d0 = 1.f, d1 = 1.f;
    if (SCALE) {
        if (r0 < n) d0 = g_dis[r0];
        if (r1 < n) d1 = g_dis[r1];
    }
#pragma unroll
    for (int j = 0; j < 8; j++) {
        int c = j * 8 + t2;
        if (r0 < n)
            *(__half2*)(out + (size_t)r0 * 64 + c) = __floats2half2_rn(acc[j][0] * d0, acc[j][1] * d0);
        if (r1 < n)
            *(__half2*)(out + (size_t)r1 * 64 + c) = __floats2half2_rn(acc[j][2] * d1, acc[j][3] * d1);
    }
}

// scale h *= dis[row] in place (layer 1 join point)
__global__ void k_scaleh(__half* __restrict__ h, int n32) {
    int i = blockIdx.x * blockDim.x + threadIdx.x;
    if (i >= n32) return;
    float d = g_dis[i >> 5];
    __half2* p = (__half2*)h;
    float2 v = __half22float2(p[i]);
    p[i] = __floats2half2_rn(v.x * d, v.y * d);
}

// ---------------- fused CSR aggregation: out[i] = relu(dis_i*(sum_j h'[s_j] + h'[i]) + b) ----------------
template <bool RELU>
__global__ void __launch_bounds__(256) k_gather64(const __half* __restrict__ h,
                                                  const float* __restrict__ b,
                                                  __half* __restrict__ out, int n) {
    int node = (blockIdx.x * blockDim.x + threadIdx.x) >> 5;
    int lane = threadIdx.x & 31;
    if (node >= n) return;
    float2 hv = __half22float2(((const __half2*)(h + (size_t)node * 64))[lane]);
    float a0 = hv.x;
    float a1 = hv.y;
    int beg = g_rowptr[node], end = g_rowptr[node + 1];
    for (int base = beg; base < end; base += 32) {
        int m = min(32, end - base);
        int s = 0;
        if (lane < m) s = g_esrc[base + lane];
#pragma unroll 4
        for (int k = 0; k < m; k++) {
            int sk = __shfl_sync(0xffffffffu, s, k);
            float2 hs = __half22float2(((const __half2*)(h + (size_t)sk * 64))[lane]);
            a0 += hs.x;
            a1 += hs.y;
        }
    }
    float dis = g_dis[node];
    float2 bb = ((const float2*)b)[lane];
    a0 = fmaf(a0, dis, bb.x);
    a1 = fmaf(a1, dis, bb.y);
    if (RELU) { a0 = fmaxf(a0, 0.f); a1 = fmaxf(a1, 0.f); }
    ((__half2*)(out + (size_t)node * 64))[lane] = __floats2half2_rn(a0, a1);
}

// ---------------- layer 3 ----------------
// t'[i] = dot(h[i,:64], W3) * dis[i]
__global__ void k_gemv64h(const __half* __restrict__ h, const float* __restrict__ w,
                          float* __restrict__ t, int n) {
    int warp = (blockIdx.x * blockDim.x + threadIdx.x) >> 5;
    int lane = threadIdx.x & 31;
    if (warp >= n) return;
    float2 hv = __half22float2(((const __half2*)(h + (size_t)warp * 64))[lane]);
    float v = hv.x * __ldg(w + 2 * lane) + hv.y * __ldg(w + 2 * lane + 1);
#pragma unroll
    for (int o = 16; o; o >>= 1) v += __shfl_down_sync(0xffffffffu, v, o);
    if (lane == 0) t[warp] = v * g_dis[warp];
}

// out[i] = sigmoid(dis_i*(sum_j t'[s_j] + t'[i]) + b3)   — warp per node
__global__ void k_out1(const float* __restrict__ t, const float* __restrict__ b3,
                       float* __restrict__ out, int n) {
    int node = (blockIdx.x * blockDim.x + threadIdx.x) >> 5;
    int lane = threadIdx.x & 31;
    if (node >= n) return;
    int beg = g_rowptr[node], end = g_rowptr[node + 1];
    float acc = 0.f;
    for (int j = beg + lane; j < end; j += 32) acc += t[g_esrc[j]];
#pragma unroll
    for (int o = 16; o; o >>= 1) acc += __shfl_xor_sync(0xffffffffu, acc, o);
    if (lane == 0) {
        float z = g_dis[node] * (acc + t[node]) + __ldg(b3);
        out[node] = 1.f / (1.f + expf(-z));
    }
}

// ---------------- launcher ----------------
extern "C" void kernel_launch(void* const* d_in, const int* in_sizes, int n_in,
                              void* d_out, int out_size) {
    // size-based input identification (robust to metadata ordering)
    int ix = -1, iei = -1, iW1 = -1, iW2 = -1, ib3 = -1;
    int i64s[3] = {-1, -1, -1};
    int n64 = 0;
    {
        int big0 = -1, big1 = -1;
        for (int i = 0; i < n_in; i++) {
            if (big0 < 0 || in_sizes[i] > in_sizes[big0]) { big1 = big0; big0 = i; }
            else if (big1 < 0 || in_sizes[i] > in_sizes[big1]) { big1 = i; }
        }
        ix = big0; iei = big1;
    }
    for (int i = 0; i < n_in; i++) {
        if (i == ix || i == iei) continue;
        int s = in_sizes[i];
        if (s == 128 * 64) iW1 = i;
        else if (s == 64 * 64) iW2 = i;
        else if (s == 1) ib3 = i;
        else if (s == 64 && n64 < 3) i64s[n64++] = i;
    }
    int ib1, ib2, iW3;
    if (i64s[0] > iW2) { iW3 = i64s[0]; ib1 = i64s[1]; ib2 = i64s[2]; }
    else               { ib1 = i64s[0]; ib2 = i64s[1]; iW3 = i64s[2]; }

    const float* x   = (const float*)d_in[ix];
    const float* W1  = (const float*)d_in[iW1];
    const float* b1  = (const float*)d_in[ib1];
    const float* W2  = (const float*)d_in[iW2];
    const float* b2  = (const float*)d_in[ib2];
    const float* W3  = (const float*)d_in[iW3];
    const float* b3  = (const float*)d_in[ib3];
    const void*  ebuf = d_in[iei];

    const int n = in_sizes[ix] / 128;
    const int E = in_sizes[iei] / 2;
    float* out = (float*)d_out;

    __half* hbuf; cudaGetSymbolAddress((void**)&hbuf, g_h16);
    __half* abuf; cudaGetSymbolAddress((void**)&abuf, g_a16);
    float*  tbuf; cudaGetSymbolAddress((void**)&tbuf, g_t);
    int*    cntp; cudaGetSymbolAddress((void**)&cntp, g_cnt);

    const int TB = 256;
    const int nBlocks = (n + TB - 1) / TB;
    const int eBlocks = (E + TB - 1) / TB;
    const int gemmBlk = (n + 63) / 64;
    const int warpBlk = ((n * 32) + TB - 1) / TB;
    const int n32     = n * 32;
    const int n32Blk  = (n32 + TB - 1) / TB;
    const int nb      = (n + 1023) / 1024;

    const int smem128 = 2 * 64 * (128 + 8) * (int)sizeof(__half);
    const int smem64  = 2 * 64 * (64 + 8) * (int)sizeof(__half);
    cudaFuncSetAttribute((const void*)k_mma64<128, false, false>,
                         cudaFuncAttributeMaxDynamicSharedMemorySize, smem128);
    cudaFuncSetAttribute((const void*)k_mma64<64, true, true>,
                         cudaFuncAttributeMaxDynamicSharedMemorySize, smem64);

    // side stream: mma1 runs concurrently with preprocessing (event fork/join)
    cudaStream_t s2;
    cudaStreamCreateWithFlags(&s2, cudaStreamNonBlocking);
    cudaEvent_t evA, evB;
    cudaEventCreateWithFlags(&evA, cudaEventDisableTiming);
    cudaEventCreateWithFlags(&evB, cudaEventDisableTiming);

    cudaEventRecord(evA, 0);
    cudaStreamWaitEvent(s2, evA, 0);
    k_mma64<128, false, false><<<gemmBlk, 128, smem128, s2>>>(x, W1, hbuf, n);
    cudaEventRecord(evB, s2);

    // preprocessing on main stream
    k_detect<<<1, TB>>>((const unsigned*)ebuf, 4096);
    cudaMemsetAsync(cntp, 0, (size_t)n * sizeof(int), 0);
    k_prep<<<eBlocks, TB>>>(ebuf, E, n);
    k_scan1<<<nb, 1024>>>(n);
    k_scan2<<<1, SCB>>>(nb);
    k_scan3<<<nBlocks, TB>>>(n, E);
    k_fill<<<eBlocks, TB>>>(ebuf, E, n);

    // join: scale mma1 output by dis
    cudaStreamWaitEvent(0, evB, 0);
    k_scaleh<<<n32Blk, TB>>>(hbuf, n32);

    // layer 1
    k_gather64<true><<<warpBlk, TB>>>(hbuf, b1, abuf, n);

    // layer 2 (epilogue applies dis scaling)
    k_mma64<64, true, true><<<gemmBlk, 128, smem64>>>(abuf, W2, hbuf, n);
    k_gather64<true><<<warpBlk, TB>>>(hbuf, b2, abuf, n);

    // layer 3
    k_gemv64h<<<warpBlk, TB>>>(abuf, W3, tbuf, n);
    k_out1<<<warpBlk, TB>>>(tbuf, b3, out, n);
}

// round 7
// speedup vs baseline: 2.0372x; 1.0375x over previous
#include <cuda_runtime.h>
#include <cuda_fp16.h>
#include <math.h>

#define NN 100000
#define EE 1600000

// Scratch (device globals: allocation-free rule)
__device__ __half g_h16[(size_t)NN * 64];   // GEMM output (gather input, dis-scaled)
__device__ __half g_a16[(size_t)NN * 64];   // gather1 output (mma2 input)
__device__ float  g_t[NN];                  // layer-3 projected scalar (dis-scaled)
__device__ int    g_cnt[NN];
__device__ float  g_dis[NN];
__device__ int    g_is64;
__device__ int    g_rowptr[NN + 1];
__device__ int    g_cursor[NN];
__device__ int    g_esrc[EE];               // CSR: src per (dst-grouped) edge
__device__ int    g_bsum[1024];
__device__ int    g_boff[1024];

// ---------------- edge dtype detection ----------------
__global__ void k_detect(const unsigned* __restrict__ buf, int nwords) {
    __shared__ unsigned s[256];
    unsigned acc = 0;
    for (int i = threadIdx.x; i < nwords; i += 256) acc |= buf[2 * i + 1];
    s[threadIdx.x] = acc;
    __syncthreads();
    for (int o = 128; o; o >>= 1) {
        if (threadIdx.x < o) s[threadIdx.x] |= s[threadIdx.x + o];
        __syncthreads();
    }
    if (threadIdx.x == 0) g_is64 = (s[0] == 0) ? 1 : 0;
}

// degree count (reads dst half of raw edge buffer, dtype-agnostic)
__global__ void k_prep(const void* __restrict__ ebuf, int E, int n) {
    int e = blockIdx.x * blockDim.x + threadIdx.x;
    if (e >= E) return;
    int d = g_is64 ? (int)((const long long*)ebuf)[(size_t)E + e]
                   : ((const int*)ebuf)[(size_t)E + e];
    if ((unsigned)d < (unsigned)n) atomicAdd(&g_cnt[d], 1);
}

// ---------------- exclusive scan of g_cnt -> g_rowptr (+ dis), warp-shuffle ----------------
__global__ void __launch_bounds__(1024) k_scan1(int n) {
    __shared__ int ws[32];
    int tid = threadIdx.x, lane = tid & 31, w = tid >> 5;
    int i = blockIdx.x * 1024 + tid;
    int v = (i < n) ? g_cnt[i] : 0;
    if (i < n) g_dis[i] = rsqrtf((float)(v + 1));  // +1 self loop
    int inc = v;
#pragma unroll
    for (int o = 1; o < 32; o <<= 1) {
        int t = __shfl_up_sync(0xffffffffu, inc, o);
        if (lane >= o) inc += t;
    }
    if (lane == 31) ws[w] = inc;
    __syncthreads();
    if (w == 0) {
        int b = ws[lane], bi = b;
#pragma unroll
        for (int o = 1; o < 32; o <<= 1) {
            int t = __shfl_up_sync(0xffffffffu, bi, o);
            if (lane >= o) bi += t;
        }
        ws[lane] = bi - b;
        if (lane == 31) g_bsum[blockIdx.x] = bi;
    }
    __syncthreads();
    if (i < n) g_rowptr[i] = ws[w] + inc - v;
}

#define SCB 1024
__global__ void k_scan2(int nb) {
    __shared__ int s[SCB];
    int tid = threadIdx.x;
    int v = (tid < nb) ? g_bsum[tid] : 0;
    s[tid] = v;
    __syncthreads();
    for (int o = 1; o < SCB; o <<= 1) {
        int t = (tid >= o) ? s[tid - o] : 0;
        __syncthreads();
        s[tid] += t;
        __syncthreads();
    }
    if (tid < nb) g_boff[tid] = s[tid] - v;
}

__global__ void k_scan3(int n, int E) {
    int i = blockIdx.x * blockDim.x + threadIdx.x;
    if (i < n) {
        int r = g_rowptr[i] + g_boff[i >> 10];
        g_rowptr[i] = r;
        g_cursor[i] = r;
    }
    if (i == 0) g_rowptr[n] = E;
}

// ---------------- CSR fill: src only (weights factored out) ----------------
__global__ void k_fill(const void* __restrict__ ebuf, int E, int n) {
    int e = blockIdx.x * blockDim.x + threadIdx.x;
    if (e >= E) return;
    int s, d;
    if (g_is64) {
        s = (int)((const long long*)ebuf)[e];
        d = (int)((const long long*)ebuf)[(size_t)E + e];
    } else {
        s = ((const int*)ebuf)[e];
        d = ((const int*)ebuf)[(size_t)E + e];
    }
    if ((unsigned)s >= (unsigned)n || (unsigned)d >= (unsigned)n) return;
    int pos = atomicAdd(&g_cursor[d], 1);
    g_esrc[pos] = s;
}

// ---------------- tensor-core GEMM: [n,K] @ [K,64] -> [n,64]fp16 (opt. dis-scaled) ----------------
template <int K, bool AHALF, bool SCALE>
__global__ void __launch_bounds__(128) k_mma64(const void* __restrict__ Xv,
                                               const float* __restrict__ W,
                                               __half* __restrict__ out, int n) {
    constexpr int PAD = 8;
    constexpr int LDA = K + PAD;
    extern __shared__ __half smem[];
    __half* sA = smem;              // 64 x LDA
    __half* sW = smem + 64 * LDA;   // 64(n) x LDA(k)  — W transposed
    const int tid = threadIdx.x;
    const int rowBase = blockIdx.x * 64;

    if (AHALF) {
        const __half* X = (const __half*)Xv;
        for (int i = tid; i < 64 * K / 8; i += 128) {
            int idx = i * 8;
            int r = idx / K, c = idx - r * K;
            uint4 v = make_uint4(0, 0, 0, 0);
            if (rowBase + r < n) v = *(const uint4*)(X + (size_t)(rowBase + r) * K + c);
            *(uint4*)&sA[r * LDA + c] = v;
        }
    } else {
        const float* X = (const float*)Xv;
        for (int i = tid; i < 64 * K / 4; i += 128) {
            int idx = i * 4;
            int r = idx / K, c = idx - r * K;
            float4 v = make_float4(0.f, 0.f, 0.f, 0.f);
            if (rowBase + r < n) v = *(const float4*)(X + (size_t)(rowBase + r) * K + c);
            *(__half2*)&sA[r * LDA + c] = __floats2half2_rn(v.x, v.y);
            *(__half2*)&sA[r * LDA + c + 2] = __floats2half2_rn(v.z, v.w);
        }
    }
    for (int i = tid; i < K * 64; i += 128) {
        int k = i >> 6, c = i & 63;
        sW[c * LDA + k] = __float2half(W[i]);
    }
    __syncthreads();

    const int wid = tid >> 5, lane = tid & 31;
    const int g = lane >> 2, t2 = (lane & 3) * 2;
    const int aRow = wid * 16;
    float acc[8][4];
#pragma unroll
    for (int j = 0; j < 8; j++)
        acc[j][0] = acc[j][1] = acc[j][2] = acc[j][3] = 0.f;

#pragma unroll
    for (int kk = 0; kk < K; kk += 16) {
        unsigned a0 = *(const unsigned*)&sA[(aRow + g) * LDA + kk + t2];
        unsigned a1 = *(const unsigned*)&sA[(aRow + g + 8) * LDA + kk + t2];
        unsigned a2 = *(const unsigned*)&sA[(aRow + g) * LDA + kk + t2 + 8];
        unsigned a3 = *(const unsigned*)&sA[(aRow + g + 8) * LDA + kk + t2 + 8];
#pragma unroll
        for (int j = 0; j < 8; j++) {
            unsigned b0 = *(const unsigned*)&sW[(j * 8 + g) * LDA + kk + t2];
            unsigned b1 = *(const unsigned*)&sW[(j * 8 + g) * LDA + kk + t2 + 8];
            asm volatile(
                "mma.sync.aligned.m16n8k16.row.col.f32.f16.f16.f32 "
                "{%0,%1,%2,%3}, {%4,%5,%6,%7}, {%8,%9}, {%0,%1,%2,%3};"
                : "+f"(acc[j][0]), "+f"(acc[j][1]), "+f"(acc[j][2]), "+f"(acc[j][3])
                : "r"(a0), "r"(a1), "r"(a2), "r"(a3), "r"(b0), "r"(b1));
        }
    }

    const int r0 = rowBase + aRow + g;
    const int r1 = r0 + 8;
    float d0 = 1.f, d1 = 1.f;
    if (SCALE) {
        if (r0 < n) d0 = g_dis[r0];
        if (r1 < n) d1 = g_dis[r1];
    }
#pragma unroll
    for (int j = 0; j < 8; j++) {
        int c = j * 8 + t2;
        if (r0 < n)
            *(__half2*)(out + (size_t)r0 * 64 + c) = __floats2half2_rn(acc[j][0] * d0, acc[j][1] * d0);
        if (r1 < n)
            *(__half2*)(out + (size_t)r1 * 64 + c) = __floats2half2_rn(acc[j][2] * d1, acc[j][3] * d1);
    }
}

// ---------------- fused CSR aggregation ----------------
// feat = relu(dis_i*(sum_j h'[s_j] + h'[i]) + b)
// PROJ=false: out[i][:] = feat (fp16).  PROJ=true: t[i] = dot(feat, w3) * dis_i.
template <bool PROJ>
__global__ void __launch_bounds__(256) k_gather64(const __half* __restrict__ h,
                                                  const float* __restrict__ b,
                                                  __half* __restrict__ out,
                                                  const float* __restrict__ w3,
                                                  float* __restrict__ tout, int n) {
    int node = (blockIdx.x * blockDim.x + threadIdx.x) >> 5;
    int lane = threadIdx.x & 31;
    if (node >= n) return;
    float2 hv = __half22float2(((const __half2*)(h + (size_t)node * 64))[lane]);
    float a0 = hv.x;
    float a1 = hv.y;
    int beg = g_rowptr[node], end = g_rowptr[node + 1];
    for (int base = beg; base < end; base += 32) {
        int m = min(32, end - base);
        int s = 0;
        if (lane < m) s = g_esrc[base + lane];
#pragma unroll 4
        for (int k = 0; k < m; k++) {
            int sk = __shfl_sync(0xffffffffu, s, k);
            float2 hs = __half22float2(((const __half2*)(h + (size_t)sk * 64))[lane]);
            a0 += hs.x;
            a1 += hs.y;
        }
    }
    float dis = g_dis[node];
    float2 bb = ((const float2*)b)[lane];
    a0 = fmaxf(fmaf(a0, dis, bb.x), 0.f);
    a1 = fmaxf(fmaf(a1, dis, bb.y), 0.f);
    if (PROJ) {
        float2 wv = ((const float2*)w3)[lane];
        float v = a0 * wv.x + a1 * wv.y;
#pragma unroll
        for (int o = 16; o; o >>= 1) v += __shfl_down_sync(0xffffffffu, v, o);
        if (lane == 0) tout[node] = v * dis;
    } else {
        ((__half2*)(out + (size_t)node * 64))[lane] = __floats2half2_rn(a0, a1);
    }
}

// out[i] = sigmoid(dis_i*(sum_j t'[s_j] + t'[i]) + b3)   — warp per node
__global__ void k_out1(const float* __restrict__ t, const float* __restrict__ b3,
                       float* __restrict__ out, int n) {
    int node = (blockIdx.x * blockDim.x + threadIdx.x) >> 5;
    int lane = threadIdx.x & 31;
    if (node >= n) return;
    int beg = g_rowptr[node], end = g_rowptr[node + 1];
    float acc = 0.f;
    for (int j = beg + lane; j < end; j += 32) acc += t[g_esrc[j]];
#pragma unroll
    for (int o = 16; o; o >>= 1) acc += __shfl_xor_sync(0xffffffffu, acc, o);
    if (lane == 0) {
        float z = g_dis[node] * (acc + t[node]) + __ldg(b3);
        out[node] = 1.f / (1.f + expf(-z));
    }
}

// ---------------- launcher ----------------
extern "C" void kernel_launch(void* const* d_in, const int* in_sizes, int n_in,
                              void* d_out, int out_size) {
    // size-based input identification (robust to metadata ordering)
    int ix = -1, iei = -1, iW1 = -1, iW2 = -1, ib3 = -1;
    int i64s[3] = {-1, -1, -1};
    int n64 = 0;
    {
        int big0 = -1, big1 = -1;
        for (int i = 0; i < n_in; i++) {
            if (big0 < 0 || in_sizes[i] > in_sizes[big0]) { big1 = big0; big0 = i; }
            else if (big1 < 0 || in_sizes[i] > in_sizes[big1]) { big1 = i; }
        }
        ix = big0; iei = big1;
    }
    for (int i = 0; i < n_in; i++) {
        if (i == ix || i == iei) continue;
        int s = in_sizes[i];
        if (s == 128 * 64) iW1 = i;
        else if (s == 64 * 64) iW2 = i;
        else if (s == 1) ib3 = i;
        else if (s == 64 && n64 < 3) i64s[n64++] = i;
    }
    int ib1, ib2, iW3;
    if (i64s[0] > iW2) { iW3 = i64s[0]; ib1 = i64s[1]; ib2 = i64s[2]; }
    else               { ib1 = i64s[0]; ib2 = i64s[1]; iW3 = i64s[2]; }

    const float* x   = (const float*)d_in[ix];
    const float* W1  = (const float*)d_in[iW1];
    const float* b1  = (const float*)d_in[ib1];
    const float* W2  = (const float*)d_in[iW2];
    const float* b2  = (const float*)d_in[ib2];
    const float* W3  = (const float*)d_in[iW3];
    const float* b3  = (const float*)d_in[ib3];
    const void*  ebuf = d_in[iei];

    const int n = in_sizes[ix] / 128;
    const int E = in_sizes[iei] / 2;
    float* out = (float*)d_out;

    __half* hbuf; cudaGetSymbolAddress((void**)&hbuf, g_h16);
    __half* abuf; cudaGetSymbolAddress((void**)&abuf, g_a16);
    float*  tbuf; cudaGetSymbolAddress((void**)&tbuf, g_t);
    int*    cntp; cudaGetSymbolAddress((void**)&cntp, g_cnt);

    const int TB = 256;
    const int nBlocks = (n + TB - 1) / TB;
    const int eBlocks = (E + TB - 1) / TB;
    const int gemmBlk = (n + 63) / 64;
    const int warpBlk = ((n * 32) + TB - 1) / TB;
    const int nb      = (n + 1023) / 1024;

    const int smem128 = 2 * 64 * (128 + 8) * (int)sizeof(__half);
    const int smem64  = 2 * 64 * (64 + 8) * (int)sizeof(__half);
    cudaFuncSetAttribute((const void*)k_mma64<128, false, true>,
                         cudaFuncAttributeMaxDynamicSharedMemorySize, smem128);
    cudaFuncSetAttribute((const void*)k_mma64<64, true, true>,
                         cudaFuncAttributeMaxDynamicSharedMemorySize, smem64);

    cudaStream_t s2;
    cudaStreamCreateWithFlags(&s2, cudaStreamNonBlocking);
    cudaEvent_t evA, evB;
    cudaEventCreateWithFlags(&evA, cudaEventDisableTiming);
    cudaEventCreateWithFlags(&evB, cudaEventDisableTiming);

    // preprocessing (main stream) up to dis availability
    k_detect<<<1, TB>>>((const unsigned*)ebuf, 4096);
    cudaMemsetAsync(cntp, 0, (size_t)n * sizeof(int), 0);
    k_prep<<<eBlocks, TB>>>(ebuf, E, n);
    k_scan1<<<nb, 1024>>>(n);          // dis ready after this

    // fork: mma1 (dis-scaled epilogue) overlaps scan2/scan3/fill
    cudaEventRecord(evA, 0);
    cudaStreamWaitEvent(s2, evA, 0);
    k_mma64<128, false, true><<<gemmBlk, 128, smem128, s2>>>(x, W1, hbuf, n);
    cudaEventRecord(evB, s2);

    k_scan2<<<1, SCB>>>(nb);
    k_scan3<<<nBlocks, TB>>>(n, E);
    k_fill<<<eBlocks, TB>>>(ebuf, E, n);

    // join
    cudaStreamWaitEvent(0, evB, 0);

    // layer 1
    k_gather64<false><<<warpBlk, TB>>>(hbuf, b1, abuf, nullptr, nullptr, n);

    // layer 2 (+ fused layer-3 projection in gather epilogue)
    k_mma64<64, true, true><<<gemmBlk, 128, smem64>>>(abuf, W2, hbuf, n);
    k_gather64<true><<<warpBlk, TB>>>(hbuf, b2, nullptr, W3, tbuf, n);

    // layer 3 scalar aggregation + sigmoid
    k_out1<<<warpBlk, TB>>>(tbuf, b3, out, n);
}

// round 8
// speedup vs baseline: 2.2222x; 1.0909x over previous
#include <cuda_runtime.h>
#include <cuda_fp16.h>
#include <math.h>

#define NN 100000
#define EE 1600000

// Scratch (device globals: allocation-free rule)
__device__ __half g_h16[(size_t)NN * 64];   // GEMM output (gather input, dis-scaled)
__device__ __half g_a16[(size_t)NN * 64];   // gather1 output (mma2 input)
__device__ float  g_t[NN];                  // layer-3 projected scalar (dis-scaled)
__device__ int    g_cnt[NN];
__device__ float  g_dis[NN];
__device__ int    g_is64;
__device__ int    g_rowptr[NN + 1];
__device__ int    g_cursor[NN];
__device__ int    g_esrc[EE];               // CSR: src per (dst-grouped) edge
__device__ int    g_bsum[1024];
__device__ int    g_boff[1024];

// ---------------- edge dtype detection ----------------
__global__ void k_detect(const unsigned* __restrict__ buf, int nwords) {
    __shared__ unsigned s[256];
    unsigned acc = 0;
    for (int i = threadIdx.x; i < nwords; i += 256) acc |= buf[2 * i + 1];
    s[threadIdx.x] = acc;
    __syncthreads();
    for (int o = 128; o; o >>= 1) {
        if (threadIdx.x < o) s[threadIdx.x] |= s[threadIdx.x + o];
        __syncthreads();
    }
    if (threadIdx.x == 0) g_is64 = (s[0] == 0) ? 1 : 0;
}

// degree count (reads dst half of raw edge buffer, dtype-agnostic)
__global__ void k_prep(const void* __restrict__ ebuf, int E, int n) {
    int e = blockIdx.x * blockDim.x + threadIdx.x;
    if (e >= E) return;
    int d = g_is64 ? (int)((const long long*)ebuf)[(size_t)E + e]
                   : ((const int*)ebuf)[(size_t)E + e];
    if ((unsigned)d < (unsigned)n) atomicAdd(&g_cnt[d], 1);
}

// ---------------- exclusive scan of g_cnt -> g_rowptr (+ dis), warp-shuffle ----------------
__global__ void __launch_bounds__(1024) k_scan1(int n) {
    __shared__ int ws[32];
    int tid = threadIdx.x, lane = tid & 31, w = tid >> 5;
    int i = blockIdx.x * 1024 + tid;
    int v = (i < n) ? g_cnt[i] : 0;
    if (i < n) g_dis[i] = rsqrtf((float)(v + 1));  // +1 self loop
    int inc = v;
#pragma unroll
    for (int o = 1; o < 32; o <<= 1) {
        int t = __shfl_up_sync(0xffffffffu, inc, o);
        if (lane >= o) inc += t;
    }
    if (lane == 31) ws[w] = inc;
    __syncthreads();
    if (w == 0) {
        int b = ws[lane], bi = b;
#pragma unroll
        for (int o = 1; o < 32; o <<= 1) {
            int t = __shfl_up_sync(0xffffffffu, bi, o);
            if (lane >= o) bi += t;
        }
        ws[lane] = bi - b;
        if (lane == 31) g_bsum[blockIdx.x] = bi;
    }
    __syncthreads();
    if (i < n) g_rowptr[i] = ws[w] + inc - v;
}

#define SCB 1024
__global__ void k_scan2(int nb) {
    __shared__ int s[SCB];
    int tid = threadIdx.x;
    int v = (tid < nb) ? g_bsum[tid] : 0;
    s[tid] = v;
    __syncthreads();
    for (int o = 1; o < SCB; o <<= 1) {
        int t = (tid >= o) ? s[tid - o] : 0;
        __syncthreads();
        s[tid] += t;
        __syncthreads();
    }
    if (tid < nb) g_boff[tid] = s[tid] - v;
}

__global__ void k_scan3(int n, int E) {
    int i = blockIdx.x * blockDim.x + threadIdx.x;
    if (i < n) {
        int r = g_rowptr[i] + g_boff[i >> 10];
        g_rowptr[i] = r;
        g_cursor[i] = r;
    }
    if (i == 0) g_rowptr[n] = E;
}

// ---------------- CSR fill: src only (weights factored out) ----------------
__global__ void k_fill(const void* __restrict__ ebuf, int E, int n) {
    int e = blockIdx.x * blockDim.x + threadIdx.x;
    if (e >= E) return;
    int s, d;
    if (g_is64) {
        s = (int)((const long long*)ebuf)[e];
        d = (int)((const long long*)ebuf)[(size_t)E + e];
    } else {
        s = ((const int*)ebuf)[e];
        d = ((const int*)ebuf)[(size_t)E + e];
    }
    if ((unsigned)s >= (unsigned)n || (unsigned)d >= (unsigned)n) return;
    int pos = atomicAdd(&g_cursor[d], 1);
    g_esrc[pos] = s;
}

// ---------------- tensor-core GEMM: [n,K] @ [K,64] -> [n,64]fp16 (dis-scaled) ----------------
// 256 threads = 8 warps, tile 128 rows x 64 cols. Warp w: rows 16w..16w+15.
template <int K, bool AHALF>
__global__ void __launch_bounds__(256) k_mma64(const void* __restrict__ Xv,
                                               const float* __restrict__ W,
                                               __half* __restrict__ out, int n) {
    constexpr int PAD = 8;
    constexpr int LDA = K + PAD;
    extern __shared__ __half smem[];
    __half* sA = smem;               // 128 x LDA
    __half* sW = smem + 128 * LDA;   // 64(n) x LDA(k) — W transposed
    const int tid = threadIdx.x;
    const int rowBase = blockIdx.x * 128;

    if (AHALF) {
        const __half* X = (const __half*)Xv;
        for (int i = tid; i < 128 * K / 8; i += 256) {
            int idx = i * 8;
            int r = idx / K, c = idx - r * K;
            uint4 v = make_uint4(0, 0, 0, 0);
            if (rowBase + r < n) v = *(const uint4*)(X + (size_t)(rowBase + r) * K + c);
            *(uint4*)&sA[r * LDA + c] = v;
        }
    } else {
        const float* X = (const float*)Xv;
        for (int i = tid; i < 128 * K / 4; i += 256) {
            int idx = i * 4;
            int r = idx / K, c = idx - r * K;
            float4 v = make_float4(0.f, 0.f, 0.f, 0.f);
            if (rowBase + r < n) v = *(const float4*)(X + (size_t)(rowBase + r) * K + c);
            *(__half2*)&sA[r * LDA + c] = __floats2half2_rn(v.x, v.y);
            *(__half2*)&sA[r * LDA + c + 2] = __floats2half2_rn(v.z, v.w);
        }
    }
    for (int i = tid; i < K * 64; i += 256) {
        int k = i >> 6, c = i & 63;
        sW[c * LDA + k] = __float2half(W[i]);
    }
    __syncthreads();

    const int wid = tid >> 5, lane = tid & 31;
    const int g = lane >> 2, t2 = (lane & 3) * 2;
    const int aRow = wid * 16;
    float acc[8][4];
#pragma unroll
    for (int j = 0; j < 8; j++)
        acc[j][0] = acc[j][1] = acc[j][2] = acc[j][3] = 0.f;

#pragma unroll
    for (int kk = 0; kk < K; kk += 16) {
        unsigned a0 = *(const unsigned*)&sA[(aRow + g) * LDA + kk + t2];
        unsigned a1 = *(const unsigned*)&sA[(aRow + g + 8) * LDA + kk + t2];
        unsigned a2 = *(const unsigned*)&sA[(aRow + g) * LDA + kk + t2 + 8];
        unsigned a3 = *(const unsigned*)&sA[(aRow + g + 8) * LDA + kk + t2 + 8];
#pragma unroll
        for (int j = 0; j < 8; j++) {
            unsigned b0 = *(const unsigned*)&sW[(j * 8 + g) * LDA + kk + t2];
            unsigned b1 = *(const unsigned*)&sW[(j * 8 + g) * LDA + kk + t2 + 8];
            asm volatile(
                "mma.sync.aligned.m16n8k16.row.col.f32.f16.f16.f32 "
                "{%0,%1,%2,%3}, {%4,%5,%6,%7}, {%8,%9}, {%0,%1,%2,%3};"
                : "+f"(acc[j][0]), "+f"(acc[j][1]), "+f"(acc[j][2]), "+f"(acc[j][3])
                : "r"(a0), "r"(a1), "r"(a2), "r"(a3), "r"(b0), "r"(b1));
        }
    }

    const int r0 = rowBase + aRow + g;
    const int r1 = r0 + 8;
    float d0 = (r0 < n) ? g_dis[r0] : 1.f;
    float d1 = (r1 < n) ? g_dis[r1] : 1.f;
#pragma unroll
    for (int j = 0; j < 8; j++) {
        int c = j * 8 + t2;
        if (r0 < n)
            *(__half2*)(out + (size_t)r0 * 64 + c) = __floats2half2_rn(acc[j][0] * d0, acc[j][1] * d0);
        if (r1 < n)
            *(__half2*)(out + (size_t)r1 * 64 + c) = __floats2half2_rn(acc[j][2] * d1, acc[j][3] * d1);
    }
}

// ---------------- fused CSR aggregation ----------------
// feat = relu(dis_i*(sum_j h'[s_j] + h'[i]) + b)
// PROJ=false: out[i][:] = feat (fp16).  PROJ=true: t[i] = dot(feat, w3) * dis_i.
template <bool PROJ>
__global__ void __launch_bounds__(256) k_gather64(const __half* __restrict__ h,
                                                  const float* __restrict__ b,
                                                  __half* __restrict__ out,
                                                  const float* __restrict__ w3,
                                                  float* __restrict__ tout, int n) {
    int node = (blockIdx.x * blockDim.x + threadIdx.x) >> 5;
    int lane = threadIdx.x & 31;
    if (node >= n) return;
    float2 hv = __half22float2(((const __half2*)(h + (size_t)node * 64))[lane]);
    float a0 = hv.x;
    float a1 = hv.y;
    int beg = g_rowptr[node], end = g_rowptr[node + 1];
    for (int base = beg; base < end; base += 32) {
        int m = min(32, end - base);
        int s = 0;
        if (lane < m) s = g_esrc[base + lane];
        int k = 0;
        // 4-way batched loads: 4 independent LDGs in flight before accumulation
        for (; k + 4 <= m; k += 4) {
            int s0 = __shfl_sync(0xffffffffu, s, k);
            int s1 = __shfl_sync(0xffffffffu, s, k + 1);
            int s2 = __shfl_sync(0xffffffffu, s, k + 2);
            int s3 = __shfl_sync(0xffffffffu, s, k + 3);
            __half2 v0 = ((const __half2*)(h + (size_t)s0 * 64))[lane];
            __half2 v1 = ((const __half2*)(h + (size_t)s1 * 64))[lane];
            __half2 v2 = ((const __half2*)(h + (size_t)s2 * 64))[lane];
            __half2 v3 = ((const __half2*)(h + (size_t)s3 * 64))[lane];
            float2 f0 = __half22float2(v0);
            float2 f1 = __half22float2(v1);
            float2 f2 = __half22float2(v2);
            float2 f3 = __half22float2(v3);
            a0 += (f0.x + f1.x) + (f2.x + f3.x);
            a1 += (f0.y + f1.y) + (f2.y + f3.y);
        }
        for (; k < m; k++) {
            int sk = __shfl_sync(0xffffffffu, s, k);
            float2 hs = __half22float2(((const __half2*)(h + (size_t)sk * 64))[lane]);
            a0 += hs.x;
            a1 += hs.y;
        }
    }
    float dis = g_dis[node];
    float2 bb = ((const float2*)b)[lane];
    a0 = fmaxf(fmaf(a0, dis, bb.x), 0.f);
    a1 = fmaxf(fmaf(a1, dis, bb.y), 0.f);
    if (PROJ) {
        float2 wv = ((const float2*)w3)[lane];
        float v = a0 * wv.x + a1 * wv.y;
#pragma unroll
        for (int o = 16; o; o >>= 1) v += __shfl_down_sync(0xffffffffu, v, o);
        if (lane == 0) tout[node] = v * dis;
    } else {
        ((__half2*)(out + (size_t)node * 64))[lane] = __floats2half2_rn(a0, a1);
    }
}

// out[i] = sigmoid(dis_i*(sum_j t'[s_j] + t'[i]) + b3)   — warp per node
__global__ void k_out1(const float* __restrict__ t, const float* __restrict__ b3,
                       float* __restrict__ out, int n) {
    int node = (blockIdx.x * blockDim.x + threadIdx.x) >> 5;
    int lane = threadIdx.x & 31;
    if (node >= n) return;
    int beg = g_rowptr[node], end = g_rowptr[node + 1];
    float acc = 0.f;
    for (int j = beg + lane; j < end; j += 32) acc += t[g_esrc[j]];
#pragma unroll
    for (int o = 16; o; o >>= 1) acc += __shfl_xor_sync(0xffffffffu, acc, o);
    if (lane == 0) {
        float z = g_dis[node] * (acc + t[node]) + __ldg(b3);
        out[node] = 1.f / (1.f + expf(-z));
    }
}

// ---------------- launcher ----------------
extern "C" void kernel_launch(void* const* d_in, const int* in_sizes, int n_in,
                              void* d_out, int out_size) {
    // size-based input identification (robust to metadata ordering)
    int ix = -1, iei = -1, iW1 = -1, iW2 = -1, ib3 = -1;
    int i64s[3] = {-1, -1, -1};
    int n64 = 0;
    {
        int big0 = -1, big1 = -1;
        for (int i = 0; i < n_in; i++) {
            if (big0 < 0 || in_sizes[i] > in_sizes[big0]) { big1 = big0; big0 = i; }
            else if (big1 < 0 || in_sizes[i] > in_sizes[big1]) { big1 = i; }
        }
        ix = big0; iei = big1;
    }
    for (int i = 0; i < n_in; i++) {
        if (i == ix || i == iei) continue;
        int s = in_sizes[i];
        if (s == 128 * 64) iW1 = i;
        else if (s == 64 * 64) iW2 = i;
        else if (s == 1) ib3 = i;
        else if (s == 64 && n64 < 3) i64s[n64++] = i;
    }
    int ib1, ib2, iW3;
    if (i64s[0] > iW2) { iW3 = i64s[0]; ib1 = i64s[1]; ib2 = i64s[2]; }
    else               { ib1 = i64s[0]; ib2 = i64s[1]; iW3 = i64s[2]; }

    const float* x   = (const float*)d_in[ix];
    const float* W1  = (const float*)d_in[iW1];
    const float* b1  = (const float*)d_in[ib1];
    const float* W2  = (const float*)d_in[iW2];
    const float* b2  = (const float*)d_in[ib2];
    const float* W3  = (const float*)d_in[iW3];
    const float* b3  = (const float*)d_in[ib3];
    const void*  ebuf = d_in[iei];

    const int n = in_sizes[ix] / 128;
    const int E = in_sizes[iei] / 2;
    float* out = (float*)d_out;

    __half* hbuf; cudaGetSymbolAddress((void**)&hbuf, g_h16);
    __half* abuf; cudaGetSymbolAddress((void**)&abuf, g_a16);
    float*  tbuf; cudaGetSymbolAddress((void**)&tbuf, g_t);
    int*    cntp; cudaGetSymbolAddress((void**)&cntp, g_cnt);

    const int TB = 256;
    const int nBlocks = (n + TB - 1) / TB;
    const int eBlocks = (E + TB - 1) / TB;
    const int gemmBlk = (n + 127) / 128;
    const int warpBlk = ((n * 32) + TB - 1) / TB;
    const int nb      = (n + 1023) / 1024;

    const int smem128 = (128 * (128 + 8) + 64 * (128 + 8)) * (int)sizeof(__half);  // 52224
    const int smem64  = (128 * (64 + 8) + 64 * (64 + 8)) * (int)sizeof(__half);    // 27648
    cudaFuncSetAttribute((const void*)k_mma64<128, false>,
                         cudaFuncAttributeMaxDynamicSharedMemorySize, smem128);
    cudaFuncSetAttribute((const void*)k_mma64<64, true>,
                         cudaFuncAttributeMaxDynamicSharedMemorySize, smem64);

    cudaStream_t s2;
    cudaStreamCreateWithFlags(&s2, cudaStreamNonBlocking);
    cudaEvent_t evA, evB;
    cudaEventCreateWithFlags(&evA, cudaEventDisableTiming);
    cudaEventCreateWithFlags(&evB, cudaEventDisableTiming);

    // preprocessing (main stream) up to dis availability
    k_detect<<<1, TB>>>((const unsigned*)ebuf, 4096);
    cudaMemsetAsync(cntp, 0, (size_t)n * sizeof(int), 0);
    k_prep<<<eBlocks, TB>>>(ebuf, E, n);
    k_scan1<<<nb, 1024>>>(n);          // dis ready after this

    // fork: mma1 (dis-scaled epilogue) overlaps scan2/scan3/fill
    cudaEventRecord(evA, 0);
    cudaStreamWaitEvent(s2, evA, 0);
    k_mma64<128, false><<<gemmBlk, 256, smem128, s2>>>(x, W1, hbuf, n);
    cudaEventRecord(evB, s2);

    k_scan2<<<1, SCB>>>(nb);
    k_scan3<<<nBlocks, TB>>>(n, E);
    k_fill<<<eBlocks, TB>>>(ebuf, E, n);

    // join
    cudaStreamWaitEvent(0, evB, 0);

    // layer 1
    k_gather64<false><<<warpBlk, TB>>>(hbuf, b1, abuf, nullptr, nullptr, n);

    // layer 2 (+ fused layer-3 projection in gather epilogue)
    k_mma64<64, true><<<gemmBlk, 256, smem64>>>(abuf, W2, hbuf, n);
    k_gather64<true><<<warpBlk, TB>>>(hbuf, b2, nullptr, W3, tbuf, n);

    // layer 3 scalar aggregation + sigmoid
    k_out1<<<warpBlk, TB>>>(tbuf, b3, out, n);
}

// round 9
// speedup vs baseline: 2.4836x; 1.1176x over previous
#include <cuda_runtime.h>
#include <cuda_fp16.h>
#include <math.h>

#define NN 100000
#define EE 1600000
#define LDA1 (128 + 8)
#define LDA2 (64 + 8)

// Scratch (device globals: allocation-free rule)
__device__ __half g_x16[(size_t)NN * 128];  // x converted to fp16
__device__ __half g_h16[(size_t)NN * 64];   // GEMM output (gather input, dis-scaled)
__device__ __half g_a16[(size_t)NN * 64];   // gather1 output (mma2 input)
__device__ __half g_w16a[64 * LDA1];        // W1 fp16, transposed [c][k]
__device__ __half g_w16b[64 * LDA2];        // W2 fp16, transposed [c][k]
__device__ float  g_t[NN];                  // layer-3 projected scalar (dis-scaled)
__device__ int    g_cnt[NN];
__device__ float  g_dis[NN];
__device__ int    g_is64;
__device__ int    g_rowptr[NN + 1];
__device__ int    g_cursor[NN];
__device__ int    g_esrc[EE];               // CSR: src per (dst-grouped) edge
__device__ int    g_bsum[1024];
__device__ int    g_boff[1024];

// ---------------- edge dtype detection ----------------
__global__ void k_detect(const unsigned* __restrict__ buf, int nwords) {
    __shared__ unsigned s[256];
    unsigned acc = 0;
    for (int i = threadIdx.x; i < nwords; i += 256) acc |= buf[2 * i + 1];
    s[threadIdx.x] = acc;
    __syncthreads();
    for (int o = 128; o; o >>= 1) {
        if (threadIdx.x < o) s[threadIdx.x] |= s[threadIdx.x + o];
        __syncthreads();
    }
    if (threadIdx.x == 0) g_is64 = (s[0] == 0) ? 1 : 0;
}

// degree count (reads dst half of raw edge buffer, dtype-agnostic)
__global__ void k_prep(const void* __restrict__ ebuf, int E, int n) {
    int e = blockIdx.x * blockDim.x + threadIdx.x;
    if (e >= E) return;
    int d = g_is64 ? (int)((const long long*)ebuf)[(size_t)E + e]
                   : ((const int*)ebuf)[(size_t)E + e];
    if ((unsigned)d < (unsigned)n) atomicAdd(&g_cnt[d], 1);
}

// ---------------- exclusive scan of g_cnt -> g_rowptr (+ dis), warp-shuffle ----------------
__global__ void __launch_bounds__(1024) k_scan1(int n) {
    __shared__ int ws[32];
    int tid = threadIdx.x, lane = tid & 31, w = tid >> 5;
    int i = blockIdx.x * 1024 + tid;
    int v = (i < n) ? g_cnt[i] : 0;
    if (i < n) g_dis[i] = rsqrtf((float)(v + 1));  // +1 self loop
    int inc = v;
#pragma unroll
    for (int o = 1; o < 32; o <<= 1) {
        int t = __shfl_up_sync(0xffffffffu, inc, o);
        if (lane >= o) inc += t;
    }
    if (lane == 31) ws[w] = inc;
    __syncthreads();
    if (w == 0) {
        int b = ws[lane], bi = b;
#pragma unroll
        for (int o = 1; o < 32; o <<= 1) {
            int t = __shfl_up_sync(0xffffffffu, bi, o);
            if (lane >= o) bi += t;
        }
        ws[lane] = bi - b;
        if (lane == 31) g_bsum[blockIdx.x] = bi;
    }
    __syncthreads();
    if (i < n) g_rowptr[i] = ws[w] + inc - v;
}

#define SCB 1024
__global__ void k_scan2(int nb) {
    __shared__ int s[SCB];
    int tid = threadIdx.x;
    int v = (tid < nb) ? g_bsum[tid] : 0;
    s[tid] = v;
    __syncthreads();
    for (int o = 1; o < SCB; o <<= 1) {
        int t = (tid >= o) ? s[tid - o] : 0;
        __syncthreads();
        s[tid] += t;
        __syncthreads();
    }
    if (tid < nb) g_boff[tid] = s[tid] - v;
}

__global__ void k_scan3(int n, int E) {
    int i = blockIdx.x * blockDim.x + threadIdx.x;
    if (i < n) {
        int r = g_rowptr[i] + g_boff[i >> 10];
        g_rowptr[i] = r;
        g_cursor[i] = r;
    }
    if (i == 0) g_rowptr[n] = E;
}

// ---------------- CSR fill: src only (weights factored out) ----------------
__global__ void k_fill(const void* __restrict__ ebuf, int E, int n) {
    int e = blockIdx.x * blockDim.x + threadIdx.x;
    if (e >= E) return;
    int s, d;
    if (g_is64) {
        s = (int)((const long long*)ebuf)[e];
        d = (int)((const long long*)ebuf)[(size_t)E + e];
    } else {
        s = ((const int*)ebuf)[e];
        d = ((const int*)ebuf)[(size_t)E + e];
    }
    if ((unsigned)s >= (unsigned)n || (unsigned)d >= (unsigned)n) return;
    int pos = atomicAdd(&g_cursor[d], 1);
    g_esrc[pos] = s;
}

// ---------------- input conversions (side stream, off critical path) ----------------
// x fp32 -> fp16
__global__ void k_cvtx(const float* __restrict__ x, int n4) {
    int i = blockIdx.x * blockDim.x + threadIdx.x;
    if (i >= n4) return;
    float4 v = ((const float4*)x)[i];
    __half2 h0 = __floats2half2_rn(v.x, v.y);
    __half2 h1 = __floats2half2_rn(v.z, v.w);
    *(uint2*)&g_x16[(size_t)i * 4] = make_uint2(*(unsigned*)&h0, *(unsigned*)&h1);
}

// W [K,64] fp32 -> transposed padded fp16 [64][LDA]
template <int K, int LDA>
__global__ void k_cvtw(const float* __restrict__ W, __half* __restrict__ out) {
    int i = blockIdx.x * blockDim.x + threadIdx.x;
    if (i >= K * 64) return;
    int k = i >> 6, c = i & 63;
    out[c * LDA + k] = __float2half(W[i]);
}

// ---------------- tensor-core GEMM: [n,K]fp16 @ W16T -> [n,64]fp16 (dis-scaled) ----------------
// 256 threads = 8 warps, tile 128 rows x 64 cols.
template <int K, int LDA>
__global__ void __launch_bounds__(256) k_mma64(const __half* __restrict__ X,
                                               const __half* __restrict__ W16,
                                               __half* __restrict__ out, int n) {
    extern __shared__ __half smem[];
    __half* sA = smem;               // 128 x LDA
    __half* sW = smem + 128 * LDA;   // 64 x LDA
    const int tid = threadIdx.x;
    const int rowBase = blockIdx.x * 128;

    // stage A: uint4 (8 halves) per op
    for (int i = tid; i < 128 * K / 8; i += 256) {
        int idx = i * 8;
        int r = idx / K, c = idx - r * K;
        uint4 v = make_uint4(0, 0, 0, 0);
        if (rowBase + r < n) v = *(const uint4*)(X + (size_t)(rowBase + r) * K + c);
        *(uint4*)&sA[r * LDA + c] = v;
    }
    // stage W: linear uint4 copy of preconverted transposed W
    for (int i = tid; i < 64 * LDA / 8; i += 256)
        ((uint4*)sW)[i] = ((const uint4*)W16)[i];
    __syncthreads();

    const int wid = tid >> 5, lane = tid & 31;
    const int g = lane >> 2, t2 = (lane & 3) * 2;
    const int aRow = wid * 16;
    float acc[8][4];
#pragma unroll
    for (int j = 0; j < 8; j++)
        acc[j][0] = acc[j][1] = acc[j][2] = acc[j][3] = 0.f;

#pragma unroll
    for (int kk = 0; kk < K; kk += 16) {
        unsigned a0 = *(const unsigned*)&sA[(aRow + g) * LDA + kk + t2];
        unsigned a1 = *(const unsigned*)&sA[(aRow + g + 8) * LDA + kk + t2];
        unsigned a2 = *(const unsigned*)&sA[(aRow + g) * LDA + kk + t2 + 8];
        unsigned a3 = *(const unsigned*)&sA[(aRow + g + 8) * LDA + kk + t2 + 8];
#pragma unroll
        for (int j = 0; j < 8; j++) {
            unsigned b0 = *(const unsigned*)&sW[(j * 8 + g) * LDA + kk + t2];
            unsigned b1 = *(const unsigned*)&sW[(j * 8 + g) * LDA + kk + t2 + 8];
            asm volatile(
                "mma.sync.aligned.m16n8k16.row.col.f32.f16.f16.f32 "
                "{%0,%1,%2,%3}, {%4,%5,%6,%7}, {%8,%9}, {%0,%1,%2,%3};"
                : "+f"(acc[j][0]), "+f"(acc[j][1]), "+f"(acc[j][2]), "+f"(acc[j][3])
                : "r"(a0), "r"(a1), "r"(a2), "r"(a3), "r"(b0), "r"(b1));
        }
    }

    const int r0 = rowBase + aRow + g;
    const int r1 = r0 + 8;
    float d0 = (r0 < n) ? g_dis[r0] : 1.f;
    float d1 = (r1 < n) ? g_dis[r1] : 1.f;
#pragma unroll
    for (int j = 0; j < 8; j++) {
        int c = j * 8 + t2;
        if (r0 < n)
            *(__half2*)(out + (size_t)r0 * 64 + c) = __floats2half2_rn(acc[j][0] * d0, acc[j][1] * d0);
        if (r1 < n)
            *(__half2*)(out + (size_t)r1 * 64 + c) = __floats2half2_rn(acc[j][2] * d1, acc[j][3] * d1);
    }
}

// ---------------- fused CSR aggregation ----------------
// feat = relu(dis_i*(sum_j h'[s_j] + h'[i]) + b)
// PROJ=false: out[i][:] = feat (fp16).  PROJ=true: t[i] = dot(feat, w3) * dis_i.
template <bool PROJ>
__global__ void __launch_bounds__(256) k_gather64(const __half* __restrict__ h,
                                                  const float* __restrict__ b,
                                                  __half* __restrict__ out,
                                                  const float* __restrict__ w3,
                                                  float* __restrict__ tout, int n) {
    int node = (blockIdx.x * blockDim.x + threadIdx.x) >> 5;
    int lane = threadIdx.x & 31;
    if (node >= n) return;
    float2 hv = __half22float2(((const __half2*)(h + (size_t)node * 64))[lane]);
    float a0 = hv.x;
    float a1 = hv.y;
    int beg = g_rowptr[node], end = g_rowptr[node + 1];
    for (int base = beg; base < end; base += 32) {
        int m = min(32, end - base);
        int s = 0;
        if (lane < m) s = g_esrc[base + lane];
        int k = 0;
        for (; k + 4 <= m; k += 4) {
            int s0 = __shfl_sync(0xffffffffu, s, k);
            int s1 = __shfl_sync(0xffffffffu, s, k + 1);
            int s2 = __shfl_sync(0xffffffffu, s, k + 2);
            int s3 = __shfl_sync(0xffffffffu, s, k + 3);
            __half2 v0 = ((const __half2*)(h + (size_t)s0 * 64))[lane];
            __half2 v1 = ((const __half2*)(h + (size_t)s1 * 64))[lane];
            __half2 v2 = ((const __half2*)(h + (size_t)s2 * 64))[lane];
            __half2 v3 = ((const __half2*)(h + (size_t)s3 * 64))[lane];
            float2 f0 = __half22float2(v0);
            float2 f1 = __half22float2(v1);
            float2 f2 = __half22float2(v2);
            float2 f3 = __half22float2(v3);
            a0 += (f0.x + f1.x) + (f2.x + f3.x);
            a1 += (f0.y + f1.y) + (f2.y + f3.y);
        }
        for (; k < m; k++) {
            int sk = __shfl_sync(0xffffffffu, s, k);
            float2 hs = __half22float2(((const __half2*)(h + (size_t)sk * 64))[lane]);
            a0 += hs.x;
            a1 += hs.y;
        }
    }
    float dis = g_dis[node];
    float2 bb = ((const float2*)b)[lane];
    a0 = fmaxf(fmaf(a0, dis, bb.x), 0.f);
    a1 = fmaxf(fmaf(a1, dis, bb.y), 0.f);
    if (PROJ) {
        float2 wv = ((const float2*)w3)[lane];
        float v = a0 * wv.x + a1 * wv.y;
#pragma unroll
        for (int o = 16; o; o >>= 1) v += __shfl_down_sync(0xffffffffu, v, o);
        if (lane == 0) tout[node] = v * dis;
    } else {
        ((__half2*)(out + (size_t)node * 64))[lane] = __floats2half2_rn(a0, a1);
    }
}

// out[i] = sigmoid(dis_i*(sum_j t'[s_j] + t'[i]) + b3)   — warp per node
__global__ void k_out1(const float* __restrict__ t, const float* __restrict__ b3,
                       float* __restrict__ out, int n) {
    int node = (blockIdx.x * blockDim.x + threadIdx.x) >> 5;
    int lane = threadIdx.x & 31;
    if (node >= n) return;
    int beg = g_rowptr[node], end = g_rowptr[node + 1];
    float acc = 0.f;
    for (int j = beg + lane; j < end; j += 32) acc += t[g_esrc[j]];
#pragma unroll
    for (int o = 16; o; o >>= 1) acc += __shfl_xor_sync(0xffffffffu, acc, o);
    if (lane == 0) {
        float z = g_dis[node] * (acc + t[node]) + __ldg(b3);
        out[node] = 1.f / (1.f + expf(-z));
    }
}

// ---------------- launcher ----------------
extern "C" void kernel_launch(void* const* d_in, const int* in_sizes, int n_in,
                              void* d_out, int out_size) {
    // size-based input identification (robust to metadata ordering)
    int ix = -1, iei = -1, iW1 = -1, iW2 = -1, ib3 = -1;
    int i64s[3] = {-1, -1, -1};
    int n64 = 0;
    {
        int big0 = -1, big1 = -1;
        for (int i = 0; i < n_in; i++) {
            if (big0 < 0 || in_sizes[i] > in_sizes[big0]) { big1 = big0; big0 = i; }
            else if (big1 < 0 || in_sizes[i] > in_sizes[big1]) { big1 = i; }
        }
        ix = big0; iei = big1;
    }
    for (int i = 0; i < n_in; i++) {
        if (i == ix || i == iei) continue;
        int s = in_sizes[i];
        if (s == 128 * 64) iW1 = i;
        else if (s == 64 * 64) iW2 = i;
        else if (s == 1) ib3 = i;
        else if (s == 64 && n64 < 3) i64s[n64++] = i;
    }
    int ib1, ib2, iW3;
    if (i64s[0] > iW2) { iW3 = i64s[0]; ib1 = i64s[1]; ib2 = i64s[2]; }
    else               { ib1 = i64s[0]; ib2 = i64s[1]; iW3 = i64s[2]; }

    const float* x   = (const float*)d_in[ix];
    const float* W1  = (const float*)d_in[iW1];
    const float* b1  = (const float*)d_in[ib1];
    const float* W2  = (const float*)d_in[iW2];
    const float* b2  = (const float*)d_in[ib2];
    const float* W3  = (const float*)d_in[iW3];
    const float* b3  = (const float*)d_in[ib3];
    const void*  ebuf = d_in[iei];

    const int n = in_sizes[ix] / 128;
    const int E = in_sizes[iei] / 2;
    float* out = (float*)d_out;

    __half* xbuf;  cudaGetSymbolAddress((void**)&xbuf, g_x16);
    __half* hbuf;  cudaGetSymbolAddress((void**)&hbuf, g_h16);
    __half* abuf;  cudaGetSymbolAddress((void**)&abuf, g_a16);
    __half* w16a;  cudaGetSymbolAddress((void**)&w16a, g_w16a);
    __half* w16b;  cudaGetSymbolAddress((void**)&w16b, g_w16b);
    float*  tbuf;  cudaGetSymbolAddress((void**)&tbuf, g_t);
    int*    cntp;  cudaGetSymbolAddress((void**)&cntp, g_cnt);

    const int TB = 256;
    const int nBlocks = (n + TB - 1) / TB;
    const int eBlocks = (E + TB - 1) / TB;
    const int gemmBlk = (n + 127) / 128;
    const int warpBlk = ((n * 32) + TB - 1) / TB;
    const int nb      = (n + 1023) / 1024;
    const int x4      = n * 32;                  // float4 count of x
    const int x4Blk   = (x4 + TB - 1) / TB;

    const int smem1 = (128 + 64) * LDA1 * (int)sizeof(__half);  // 52224
    const int smem2 = (128 + 64) * LDA2 * (int)sizeof(__half);  // 27648
    cudaFuncSetAttribute((const void*)k_mma64<128, LDA1>,
                         cudaFuncAttributeMaxDynamicSharedMemorySize, smem1);
    cudaFuncSetAttribute((const void*)k_mma64<64, LDA2>,
                         cudaFuncAttributeMaxDynamicSharedMemorySize, smem2);

    cudaStream_t s2;
    cudaStreamCreateWithFlags(&s2, cudaStreamNonBlocking);
    cudaEvent_t evA, evB;
    cudaEventCreateWithFlags(&evA, cudaEventDisableTiming);
    cudaEventCreateWithFlags(&evB, cudaEventDisableTiming);

    // side stream: conversions independent of edges start immediately
    k_cvtw<128, LDA1><<<(128 * 64 + TB - 1) / TB, TB, 0, s2>>>(W1, w16a);
    k_cvtw<64, LDA2><<<(64 * 64 + TB - 1) / TB, TB, 0, s2>>>(W2, w16b);
    k_cvtx<<<x4Blk, TB, 0, s2>>>(x, x4);

    // main stream: preprocessing up to dis availability
    k_detect<<<1, TB>>>((const unsigned*)ebuf, 4096);
    cudaMemsetAsync(cntp, 0, (size_t)n * sizeof(int), 0);
    k_prep<<<eBlocks, TB>>>(ebuf, E, n);
    k_scan1<<<nb, 1024>>>(n);          // dis ready
    cudaEventRecord(evA, 0);

    // side stream: mma1 (needs dis for epilogue scaling) overlaps scan2/scan3/fill
    cudaStreamWaitEvent(s2, evA, 0);
    k_mma64<128, LDA1><<<gemmBlk, 256, smem1, s2>>>(xbuf, w16a, hbuf, n);
    cudaEventRecord(evB, s2);

    k_scan2<<<1, SCB>>>(nb);
    k_scan3<<<nBlocks, TB>>>(n, E);
    k_fill<<<eBlocks, TB>>>(ebuf, E, n);

    // join
    cudaStreamWaitEvent(0, evB, 0);

    // layer 1
    k_gather64<false><<<warpBlk, TB>>>(hbuf, b1, abuf, nullptr, nullptr, n);

    // layer 2 (+ fused layer-3 projection in gather epilogue)
    k_mma64<64, LDA2><<<gemmBlk, 256, smem2>>>(abuf, w16b, hbuf, n);
    k_gather64<true><<<warpBlk, TB>>>(hbuf, b2, nullptr, W3, tbuf, n);

    // layer 3 scalar aggregation + sigmoid
    k_out1<<<warpBlk, TB>>>(tbuf, b3, out, n);
}